// round 13
// baseline (speedup 1.0000x reference)
#include <cuda_runtime.h>
#include <cuda_fp16.h>
#include <math.h>

// Problem dims
#define NN   2000
#define NE   3000
#define BB   16
#define CC   17
#define WW   12
#define DD   16
#define OO   256
#define KK   3
#define NBB  3
#define BC   (BB*CC)    // 272
#define NCP  320        // fp32 Y stride
#define KPAD 2048       // fp16 padded k-stride (zero-init padding is load-bearing)
#define KCQ  (KK*CC)    // 51
#define O4   64
#define O8   32
#define O2   128

#define STAGES 4
#define TILE_HALVES (64*72)            // one A or B tile in halves
#define STAGE_BYTES (2*TILE_HALVES*2)  // A+B per stage = 18432 B
#define GEMM_SMEM   (STAGES*STAGE_BYTES) // 73728 B

// kH2 pipeline: 3-stage ring x (25 rows x 256 cols fp32), i-chunks of 125 rows
#define H2_ROWS   25
#define H2_TILE   (H2_ROWS*256)                  // floats per stage
#define H2_CHUNK  125
#define H2_NSTAGE 5                               // 125 rows per i-chunk
#define H2_SMEM   ((3*H2_TILE + 16*128) * 4)      // 84992 B -> 2 blocks/SM

// ---------------- scratch (device globals; no runtime alloc) ----------------
__device__ float g_S[NN*NN];                 // fixed-adj path only
__device__ __half g_Sh[NN*KPAD];             // fp16 S (pad cols zero)
__device__ __half g_XtT[NCP*KPAD];           // fp16 X^T rows n=b*17+c, cols m
__device__ __half g_Y1T[NCP*KPAD];           // fp16 Y1^T
__device__ float g_rrow[NN];
__device__ float g_Y1[NN*NCP];
__device__ float g_Y2[NN*NCP];
__device__ __half g_Wh[NN*KCQ*O4];           // adaptive weights (fp16, 13 MB)
__device__ float g_bias[NN*OO];
__device__ float g_wws[NN*O8];
__device__ float g_wwt[NN*O2];
__device__ float g_xw[BB*NN];
__device__ float g_se[BB*NE];
__device__ float g_mpT[NE*BB];
__device__ float g_xm[NN*BB];
__device__ float g_rsum[NN];

__device__ __forceinline__ float decode_scalar(const int* p) {
    int iv = *p;
    return (iv > -1000000 && iv < 1000000) ? (float)iv : __int_as_float(iv);
}

__device__ __forceinline__ unsigned cvta_s(const void* p) {
    return (unsigned)__cvta_generic_to_shared(p);
}

// ---------------- fused: S0 = relu(ne@ne^T) diag=stay, softmax -> fp16 S ----------------
// 2 rows per block (grid 1000): ~80 regs -> 2-3 blocks/SM for latency hiding
__global__ __launch_bounds__(256) void kS0Softmax(const float* __restrict__ ne,
                                                  const float* __restrict__ adj,
                                                  const int* __restrict__ stay,
                                                  const int* __restrict__ fixedp) {
    __shared__ float2 red2[256];
    int i0 = blockIdx.x * 2;
    int t = threadIdx.x;
    bool isfixed = (decode_scalar(fixedp) != 0.0f);
    float sc = decode_scalar(stay);

    float nei[2][16];
#pragma unroll
    for (int r = 0; r < 2; r++)
#pragma unroll
        for (int q = 0; q < 4; q++) {
            float4 v = __ldg((const float4*)&ne[(size_t)(i0 + r) * DD + q * 4]);
            nei[r][q * 4 + 0] = v.x; nei[r][q * 4 + 1] = v.y;
            nei[r][q * 4 + 2] = v.z; nei[r][q * 4 + 3] = v.w;
        }

    float vals[2][8];
    float mx0 = -1e30f, mx1 = -1e30f;
#pragma unroll
    for (int jj = 0; jj < 8; jj++) {
        int j = t + jj * 256;
        if (j < NN) {
            float nej[16];
#pragma unroll
            for (int q = 0; q < 4; q++) {
                float4 v = __ldg((const float4*)&ne[(size_t)j * DD + q * 4]);
                nej[q * 4 + 0] = v.x; nej[q * 4 + 1] = v.y;
                nej[q * 4 + 2] = v.z; nej[q * 4 + 3] = v.w;
            }
#pragma unroll
            for (int r = 0; r < 2; r++) {
                float acc = 0.f;
#pragma unroll
                for (int d = 0; d < 16; d++) acc += nei[r][d] * nej[d];
                vals[r][jj] = (j == i0 + r) ? sc : fmaxf(acc, 0.f);
            }
            mx0 = fmaxf(mx0, vals[0][jj]);
            mx1 = fmaxf(mx1, vals[1][jj]);
        } else {
            vals[0][jj] = -1e30f; vals[1][jj] = -1e30f;
        }
    }
    red2[t] = make_float2(mx0, mx1); __syncthreads();
    for (int s = 128; s > 0; s >>= 1) {
        if (t < s) {
            float2 o = red2[t + s];
            red2[t].x = fmaxf(red2[t].x, o.x);
            red2[t].y = fmaxf(red2[t].y, o.y);
        }
        __syncthreads();
    }
    mx0 = red2[0].x; mx1 = red2[0].y; __syncthreads();

    float s0 = 0.f, s1 = 0.f;
#pragma unroll
    for (int jj = 0; jj < 8; jj++) {
        int j = t + jj * 256;
        if (j < NN) {
            float e0, e1;
            if (!isfixed) {
                e0 = expf(vals[0][jj] - mx0);
                e1 = expf(vals[1][jj] - mx1);
            } else {
                e0 = __ldg(&adj[(size_t)(i0 + 0) * NN + j]) * expf(vals[0][jj]);
                e1 = __ldg(&adj[(size_t)(i0 + 1) * NN + j]) * expf(vals[1][jj]);
            }
            vals[0][jj] = e0; vals[1][jj] = e1;
            s0 += e0; s1 += e1;
        }
    }
    red2[t] = make_float2(s0, s1); __syncthreads();
    for (int s = 128; s > 0; s >>= 1) {
        if (t < s) {
            float2 o = red2[t + s];
            red2[t].x += o.x; red2[t].y += o.y;
        }
        __syncthreads();
    }
    float inv0 = 1.f / red2[0].x, inv1 = 1.f / red2[0].y;

    if (!isfixed) {
#pragma unroll
        for (int jj = 0; jj < 8; jj++) {
            int j = t + jj * 256;
            if (j < NN) {
                g_Sh[(size_t)(i0 + 0) * KPAD + j] = __float2half(vals[0][jj] * inv0);
                g_Sh[(size_t)(i0 + 1) * KPAD + j] = __float2half(vals[1][jj] * inv1);
            }
        }
    } else {
#pragma unroll
        for (int jj = 0; jj < 8; jj++) {
            int j = t + jj * 256;
            if (j < NN) {
                g_S[(size_t)(i0 + 0) * NN + j] = vals[0][jj];
                g_S[(size_t)(i0 + 1) * NN + j] = vals[1][jj];
            }
        }
        if (t < 2) g_rrow[i0 + t] = (t == 0) ? inv0 : inv1;
    }
}

// fixed-adj path only: column j scaled by 1/rowsum[j], emit fp16
__global__ void kColDivH(const int* __restrict__ fixedp) {
    if (decode_scalar(fixedp) == 0.0f) return;
    int idx = blockIdx.x * blockDim.x + threadIdx.x;
    int stride = gridDim.x * blockDim.x;
    for (; idx < NN * NN; idx += stride) {
        int i = idx / NN, j = idx - i * NN;
        g_Sh[(size_t)i * KPAD + j] = __float2half(g_S[idx] * g_rrow[j]);
    }
}

// ---------------- prep: bias/wws/wwt + gnn rowsum + temporal + packT + hodge se/mpT ----------------
__global__ __launch_bounds__(256) void kPrep(const float* __restrict__ ne,
                                             const float* __restrict__ bp,
                                             const float* __restrict__ wwsp,
                                             const float* __restrict__ wwtp,
                                             const float* __restrict__ gw,
                                             const float* __restrict__ xwin,
                                             const float* __restrict__ Tp,
                                             const float* __restrict__ x,
                                             const float* __restrict__ xew,
                                             const int* __restrict__ bidx,
                                             const float* __restrict__ lw,
                                             const float* __restrict__ lb,
                                             const int* __restrict__ jumpp) {
    __shared__ float nn[16];
    __shared__ float red[256];
    int n = blockIdx.x, t = threadIdx.x;
    if (t < 16) nn[t] = ne[n * DD + t];
    __syncthreads();
    {
        float acc = 0.f;
#pragma unroll
        for (int d = 0; d < 16; d++) acc += nn[d] * bp[d * OO + t];
        g_bias[n * OO + t] = acc;
    }
    if (t < O8) {
        float a = 0.f;
#pragma unroll
        for (int d = 0; d < 16; d++) a += nn[d] * wwsp[d * O8 + t];
        g_wws[n * O8 + t] = a;
    }
    if (t < O2) {
        float a = 0.f;
#pragma unroll
        for (int d = 0; d < 16; d++) a += nn[d] * wwtp[d * O2 + t];
        g_wwt[n * O2 + t] = a;
    }
    {
        float s = 0.f;
        for (int j = t; j < NN; j += 256) s += gw[(size_t)n * NN + j];
        red[t] = s; __syncthreads();
        for (int st = 128; st > 0; st >>= 1) { if (t < st) red[t] += red[t + st]; __syncthreads(); }
        if (t == 0) g_rsum[n] = red[0];
    }
    if (t < BB) {
        float s = 0.f;
#pragma unroll
        for (int w = 0; w < WW; w++) s += xwin[(size_t)t * WW * NN + (size_t)w * NN + n] * Tp[w];
        g_xw[t * NN + n] = s;
    }
    for (int l = t; l < BC; l += 256) {
        int b = l / CC, c = l - b * CC;
        g_XtT[(size_t)l * KPAD + n] = __float2half(x[(size_t)(b * NN + n) * CC + c]);
    }
    // hodge se + mpT init: one element per global thread
    {
        int gid = n * 256 + t;
        if (gid < BB * NE) {
            int b = gid / NE, i = gid - b * NE;
            float w0 = lw[0], b0 = lb[0];
            float jc = decode_scalar(jumpp);
            float s = 0.f, tt = 0.f;
#pragma unroll
            for (int f = 0; f < NBB; f++) {
                int wv = bidx[f];
                float v = xew[(size_t)b * WW * NE + (size_t)wv * NE + i] * w0 + b0;
                s += v;
                tt += (float)(NBB - 1 - f) * v;
            }
            g_se[gid] = s;
            g_mpT[i * BB + b] = jc * tt;
        }
    }
}

// ---------------- fp16 MMA GEMM, cp.async 4-stage pipeline: C(2000,320) = S @ B ----------------
__global__ __launch_bounds__(256) void kGemmMMA(int phase) {
    extern __shared__ __half sm[];
    const __half* __restrict__ Bt = phase ? g_Y1T : g_XtT;
    float* __restrict__ Y = phase ? g_Y2 : g_Y1;
    int m0 = blockIdx.x * 64, n0 = blockIdx.y * 64;
    int t = threadIdx.x;
    int wid = t >> 5, lane = t & 31;
    int wm = (wid & 3) * 16, wn = (wid >> 2) * 32;
    float acc[4][4] = {};

    int row0 = t >> 3, seg = t & 7;
    int row1 = row0 + 32;
    int gmA0 = m0 + row0; if (gmA0 > NN - 1) gmA0 = NN - 1;
    int gmA1 = m0 + row1; if (gmA1 > NN - 1) gmA1 = NN - 1;
    const __half* a0p = &g_Sh[(size_t)gmA0 * KPAD + seg * 8];
    const __half* a1p = &g_Sh[(size_t)gmA1 * KPAD + seg * 8];
    const __half* b0p = &Bt[(size_t)(n0 + row0) * KPAD + seg * 8];
    const __half* b1p = &Bt[(size_t)(n0 + row1) * KPAD + seg * 8];

    unsigned smb = cvta_s(sm);
    unsigned dA0 = smb + (row0 * 72 + seg * 8) * 2;
    unsigned dA1 = smb + (row1 * 72 + seg * 8) * 2;
    unsigned dB0 = dA0 + TILE_HALVES * 2;
    unsigned dB1 = dA1 + TILE_HALVES * 2;

    int r = lane & 7, f = lane >> 3;
    unsigned aOff = smb + ((wm + ((f & 1) << 3) + r) * 72 + ((f >> 1) << 3)) * 2;
    unsigned bOff = smb + TILE_HALVES * 2 + ((wn + ((f >> 1) << 3) + r) * 72 + ((f & 1) << 3)) * 2;

#define ISSUE(KC) do {                                                          \
    if ((KC) < KPAD / 64) {                                                     \
        unsigned sb_ = ((KC) & (STAGES - 1)) * STAGE_BYTES;                     \
        size_t off_ = (size_t)(KC) * 64;                                        \
        asm volatile("cp.async.cg.shared.global [%0], [%1], 16;" :: "r"(dA0 + sb_), "l"(a0p + off_)); \
        asm volatile("cp.async.cg.shared.global [%0], [%1], 16;" :: "r"(dA1 + sb_), "l"(a1p + off_)); \
        asm volatile("cp.async.cg.shared.global [%0], [%1], 16;" :: "r"(dB0 + sb_), "l"(b0p + off_)); \
        asm volatile("cp.async.cg.shared.global [%0], [%1], 16;" :: "r"(dB1 + sb_), "l"(b1p + off_)); \
    }                                                                           \
    asm volatile("cp.async.commit_group;");                                     \
} while (0)

    ISSUE(0); ISSUE(1); ISSUE(2);

    for (int kc = 0; kc < KPAD / 64; kc++) {
        asm volatile("cp.async.wait_group %0;" :: "n"(STAGES - 2));
        __syncthreads();
        ISSUE(kc + 3);
        unsigned sb = (kc & (STAGES - 1)) * STAGE_BYTES;
        unsigned aB = aOff + sb, bB = bOff + sb;
#pragma unroll
        for (int ks = 0; ks < 4; ks++) {
            unsigned a0, a1, a2, a3;
            asm volatile("ldmatrix.sync.aligned.m8n8.x4.shared.b16 {%0,%1,%2,%3}, [%4];"
                         : "=r"(a0), "=r"(a1), "=r"(a2), "=r"(a3)
                         : "r"(aB + ks * 32));
            unsigned b00, b01, b10, b11;
            asm volatile("ldmatrix.sync.aligned.m8n8.x4.shared.b16 {%0,%1,%2,%3}, [%4];"
                         : "=r"(b00), "=r"(b01), "=r"(b10), "=r"(b11)
                         : "r"(bB + ks * 32));
            unsigned b20, b21, b30, b31;
            asm volatile("ldmatrix.sync.aligned.m8n8.x4.shared.b16 {%0,%1,%2,%3}, [%4];"
                         : "=r"(b20), "=r"(b21), "=r"(b30), "=r"(b31)
                         : "r"(bB + ks * 32 + 16 * 144));
#define MMA16816(ACC, B0, B1) \
            asm volatile("mma.sync.aligned.m16n8k16.row.col.f32.f16.f16.f32 " \
                "{%0,%1,%2,%3}, {%4,%5,%6,%7}, {%8,%9}, {%0,%1,%2,%3};" \
                : "+f"(ACC[0]), "+f"(ACC[1]), "+f"(ACC[2]), "+f"(ACC[3]) \
                : "r"(a0), "r"(a1), "r"(a2), "r"(a3), "r"(B0), "r"(B1))
            MMA16816(acc[0], b00, b01);
            MMA16816(acc[1], b10, b11);
            MMA16816(acc[2], b20, b21);
            MMA16816(acc[3], b30, b31);
#undef MMA16816
        }
    }
#undef ISSUE

    int grp = lane >> 2, tid4 = lane & 3;
    int r0 = m0 + wm + grp, r1 = r0 + 8;
#pragma unroll
    for (int nj = 0; nj < 4; nj++) {
        int col = n0 + wn + nj * 8 + tid4 * 2;
        if (r0 < NN) {
            *(float2*)&Y[(size_t)r0 * NCP + col] = make_float2(acc[nj][0], acc[nj][1]);
            if (phase == 0) {
                g_Y1T[(size_t)col * KPAD + r0]       = __float2half(acc[nj][0]);
                g_Y1T[(size_t)(col + 1) * KPAD + r0] = __float2half(acc[nj][1]);
            }
        }
        if (r1 < NN) {
            *(float2*)&Y[(size_t)r1 * NCP + col] = make_float2(acc[nj][2], acc[nj][3]);
            if (phase == 0) {
                g_Y1T[(size_t)col * KPAD + r1]       = __float2half(acc[nj][2]);
                g_Y1T[(size_t)(col + 1) * KPAD + r1] = __float2half(acc[nj][3]);
            }
        }
    }
}

// ---------------- adaptive weights (fp16 out, half2 stores) ----------------
__global__ void kWeights(const float* __restrict__ ne, const float* __restrict__ wp) {
    __shared__ float nes[32][17];
    int j0 = blockIdx.x * 512;
    int n0 = blockIdx.y * 32;
    int t = threadIdx.x;
    for (int l = t; l < 32 * 16; l += 256) {
        int r = l >> 4, d = l & 15;
        nes[r][d] = (n0 + r < NN) ? ne[(n0 + r) * DD + d] : 0.f;
    }
    __syncthreads();
    int j = j0 + t * 2;
    if (j < KCQ * O4) {
        float w0[16], w1[16];
        bool ok1 = (j + 1 < KCQ * O4);
#pragma unroll
        for (int d = 0; d < 16; d++) {
            w0[d] = wp[d * (KCQ * O4) + j];
            w1[d] = ok1 ? wp[d * (KCQ * O4) + j + 1] : 0.f;
        }
        for (int r = 0; r < 32; r++) {
            int n = n0 + r;
            if (n >= NN) break;
            float a0 = 0.f, a1 = 0.f;
#pragma unroll
            for (int d = 0; d < 16; d++) { a0 += nes[r][d] * w0[d]; a1 += nes[r][d] * w1[d]; }
            *(__half2*)&g_Wh[(size_t)n * (KCQ * O4) + j] = __floats2half2_rn(a0, a1);
        }
    }
}

// ---------------- hodge GEMV via cp.async pipeline ----------------
// mpT[j,b] += sum_ii se[b, i0+ii] * hodge[i0+ii, j]
// 3-stage ring, 25 rows x 256 cols fp32 per stage, 125-row chunks -> grid (12,24), 2 blocks/SM
__global__ __launch_bounds__(256) void kH2(const float* __restrict__ hodge) {
    extern __shared__ float h2s[];
    float* tile = h2s;                         // [3][25][256]
    float* ses  = h2s + 3 * H2_TILE;           // [16][128]
    int j0 = blockIdx.x * 256;
    int i0 = blockIdx.y * H2_CHUNK;
    int t = threadIdx.x;
    for (int l = t; l < 16 * H2_CHUNK; l += 256) {
        int b = l / H2_CHUNK, ii = l % H2_CHUNK;
        ses[b * 128 + ii] = g_se[b * NE + i0 + ii];
    }
    unsigned smb = cvta_s(tile);

#define H2_ISSUE(S, RING) do {                                                   \
    if ((S) < H2_NSTAGE) {                                                       \
        unsigned dst0 = smb + (RING) * (H2_TILE * 4);                            \
        const float* src0 = hodge + (size_t)(i0 + (S) * H2_ROWS) * NE + j0;      \
        _Pragma("unroll")                                                        \
        for (int it = 0; it < 7; it++) {                                         \
            int idx = t + it * 256;                                              \
            if (idx < H2_ROWS * 64) {                                            \
                int row = idx >> 6, c4 = idx & 63;                               \
                if (j0 + c4 * 4 + 4 <= NE) {                                     \
                    asm volatile("cp.async.cg.shared.global [%0], [%1], 16;" ::  \
                        "r"(dst0 + (unsigned)(row * 256 + c4 * 4) * 4),          \
                        "l"(src0 + (size_t)row * NE + c4 * 4));                  \
                }                                                                \
            }                                                                    \
        }                                                                        \
    }                                                                            \
    asm volatile("cp.async.commit_group;");                                      \
} while (0)

    H2_ISSUE(0, 0); H2_ISSUE(1, 1);

    float acc[16] = {};
    int ring = 0;
    for (int s = 0; s < H2_NSTAGE; s++) {
        asm volatile("cp.async.wait_group %0;" :: "n"(1));
        __syncthreads();
        int nring = (ring + 2 >= 3) ? ring - 1 : ring + 2;
        H2_ISSUE(s + 2, nring);
        const float* tl = tile + ring * H2_TILE + t;
        int ibase = s * H2_ROWS;
#pragma unroll 5
        for (int i = 0; i < H2_ROWS; i++) {
            float h = tl[i * 256];
#pragma unroll
            for (int b = 0; b < 16; b++)
                acc[b] += ses[b * 128 + ibase + i] * h;
        }
        ring = (ring + 1 == 3) ? 0 : ring + 1;
        __syncthreads();
    }
#undef H2_ISSUE

    int j = j0 + t;
    if (j < NE) {
#pragma unroll
        for (int b = 0; b < 16; b++) atomicAdd(&g_mpT[j * BB + b], acc[b]);
    }
}

// xm[n,b] = (1/nb) sum_e mpT[e,b] * inc[n,e]  — float4 staging, guarded tail (NE % 64 != 0)
__global__ void kH3(const float* __restrict__ inc, int nb) {
    __shared__ float incs[16][68];   // row stride 272B (16B multiple)
    __shared__ float mps[64][20];    // row stride 80B (16B multiple)
    int n0 = blockIdx.x * 16;
    int t = threadIdx.x;
    int nr = t >> 4, b = t & 15;
    int ir = t >> 4, ie4 = (t & 15) * 4;    // incs[ir][ie4..ie4+3]
    int me = t >> 2, mb4 = (t & 3) * 4;     // mps[me][mb4..mb4+3]
    float acc = 0.f;
    for (int e0 = 0; e0 < NE; e0 += 64) {
        if (e0 + 64 <= NE) {
            float4 v = *(const float4*)&inc[(size_t)(n0 + ir) * NE + e0 + ie4];
            *(float4*)&incs[ir][ie4] = v;
            float4 w = *(const float4*)&g_mpT[(size_t)(e0 + me) * BB + mb4];
            *(float4*)&mps[me][mb4] = w;
        } else {
#pragma unroll
            for (int k = 0; k < 4; k++) {
                int e = e0 + ie4 + k;
                incs[ir][ie4 + k] = (e < NE) ? inc[(size_t)(n0 + ir) * NE + e] : 0.f;
            }
            bool okm = (e0 + me < NE);
#pragma unroll
            for (int k = 0; k < 4; k++)
                mps[me][mb4 + k] = okm ? g_mpT[(size_t)(e0 + me) * BB + mb4 + k] : 0.f;
        }
        __syncthreads();
#pragma unroll 8
        for (int ee = 0; ee < 64; ee++) acc += incs[nr][ee] * mps[ee][b];
        __syncthreads();
    }
    g_xm[(n0 + nr) * BB + b] = acc / (float)nb;
}

// ---------------- fused output: diffusion (0:64) + ZFC/temporal/supra (64:256) ----------------
__global__ __launch_bounds__(256) void kOut(const float* __restrict__ x,
                                            const float* __restrict__ zin,
                                            const float* __restrict__ gnnb,
                                            float* __restrict__ out) {
    __shared__ float ws[KCQ * O4];
    __shared__ float xs[BB][KCQ + 1];
    int n = blockIdx.x, t = threadIdx.x;
    {
        const uint4* wp4 = (const uint4*)&g_Wh[(size_t)n * (KCQ * O4)];
        for (int l = t; l < 408; l += 256) {
            uint4 v = wp4[l];
            const __half* h = (const __half*)&v;
#pragma unroll
            for (int k = 0; k < 8; k++) ws[l * 8 + k] = __half2float(h[k]);
        }
    }
    for (int l = t; l < BB * KCQ; l += 256) {
        int b = l / KCQ, kc = l % KCQ;
        int k = kc / CC, c = kc % CC;
        float v;
        if (k == 0)      v = x[(size_t)(b * NN + n) * CC + c];
        else if (k == 1) v = g_Y1[(size_t)n * NCP + b * CC + c];
        else             v = g_Y2[(size_t)n * NCP + b * CC + c];
        xs[b][kc] = v;
    }
    __syncthreads();
    {
        int o = t & 63, bq = t >> 6;
        int b0 = bq * 4;
        float a0 = 0.f, a1 = 0.f, a2 = 0.f, a3 = 0.f;
        for (int kc = 0; kc < KCQ; kc++) {
            float w = ws[kc * O4 + o];
            a0 += xs[b0 + 0][kc] * w;
            a1 += xs[b0 + 1][kc] * w;
            a2 += xs[b0 + 2][kc] * w;
            a3 += xs[b0 + 3][kc] * w;
        }
        float bi = g_bias[n * OO + o];
        out[(size_t)((b0 + 0) * NN + n) * OO + o] = a0 + bi;
        out[(size_t)((b0 + 1) * NN + n) * OO + o] = a1 + bi;
        out[(size_t)((b0 + 2) * NN + n) * OO + o] = a2 + bi;
        out[(size_t)((b0 + 3) * NN + n) * OO + o] = a3 + bi;
    }
    if (t < 192) {
        int j = t, o;
        int q = 0; float zr = 0.f, gb = 0.f, wwtv = 0.f, wwsv = 0.f;
        if (j < 32) {
            int k = n * 32 + j;
            q = k / NN; int m = k - q * NN;
            zr = g_rsum[m]; gb = gnnb[m];
            o = 64 + j;
        } else if (j < 160) {
            wwtv = g_wwt[n * O2 + (j - 32)];
            o = 96 + (j - 32);
        } else {
            wwsv = g_wws[n * O8 + (j - 160)];
            o = 224 + (j - 160);
        }
        float bi = g_bias[n * OO + o];
#pragma unroll
        for (int b = 0; b < BB; b++) {
            float v;
            if (j < 32)       v = fmaxf(zin[b * 32 + q] * zr + gb, 0.f);
            else if (j < 160) v = g_xw[b * NN + n] * wwtv;
            else              v = g_xm[n * BB + b] * wwsv;
            out[(size_t)(b * NN + n) * OO + o] = v + bi;
        }
    }
}

// ---------------- launch ----------------
extern "C" void kernel_launch(void* const* d_in, const int* in_sizes, int n_in,
                              void* d_out, int out_size) {
    const float* x     = (const float*)d_in[0];
    const float* xwin  = (const float*)d_in[1];
    const float* ne    = (const float*)d_in[2];
    const int*   fixed = (const int*)  d_in[3];
    const float* adj   = (const float*)d_in[4];
    const int*   stay  = (const int*)  d_in[5];
    const int*   jump  = (const int*)  d_in[6];
    const float* zin   = (const float*)d_in[7];
    const float* hodge = (const float*)d_in[8];
    const float* xew   = (const float*)d_in[9];
    const float* inc   = (const float*)d_in[10];
    const float* wp    = (const float*)d_in[11];
    const float* wwsp  = (const float*)d_in[12];
    const float* wwtp  = (const float*)d_in[13];
    const float* bp    = (const float*)d_in[14];
    const float* Tp    = (const float*)d_in[15];
    const float* lw    = (const float*)d_in[16];
    const float* lb    = (const float*)d_in[17];
    const float* gw    = (const float*)d_in[18];
    const float* gnnb  = (const float*)d_in[19];
    const int*   bidx  = (const int*)  d_in[20];
    float* out = (float*)d_out;
    int nb = in_sizes[20];   // NB = 3

    cudaFuncSetAttribute(kGemmMMA, cudaFuncAttributeMaxDynamicSharedMemorySize, GEMM_SMEM);
    cudaFuncSetAttribute(kH2, cudaFuncAttributeMaxDynamicSharedMemorySize, H2_SMEM);

    // order: capture slot #4 = kH2 — verify the occupancy re-grid
    kPrep<<<NN, 256>>>(ne, bp, wwsp, wwtp, gw, xwin, Tp, x, xew, bidx, lw, lb, jump);
    kS0Softmax<<<1000, 256>>>(ne, adj, stay, fixed);
    kColDivH<<<148, 256>>>(fixed);           // dead on softmax path
    kH2<<<dim3(12, 24), 256, H2_SMEM>>>(hodge);
    kGemmMMA<<<dim3(32, 5), 256, GEMM_SMEM>>>(0);
    kGemmMMA<<<dim3(32, 5), 256, GEMM_SMEM>>>(1);
    kWeights<<<dim3(7, 63), 256>>>(ne, wp);
    kH3<<<125, 256>>>(inc, nb);
    kOut<<<NN, 256>>>(x, zin, gnnb, out);
}

// round 14
// speedup vs baseline: 1.0275x; 1.0275x over previous
#include <cuda_runtime.h>
#include <cuda_fp16.h>
#include <math.h>

// Problem dims
#define NN   2000
#define NE   3000
#define BB   16
#define CC   17
#define WW   12
#define DD   16
#define OO   256
#define KK   3
#define NBB  3
#define BC   (BB*CC)    // 272
#define NCP  320        // fp32 Y stride
#define KPAD 2048       // fp16 padded k-stride (zero-init padding is load-bearing)
#define KCQ  (KK*CC)    // 51
#define O4   64
#define O8   32
#define O2   128

#define STAGES 4
#define TILE_HALVES (64*72)            // one A or B tile in halves
#define STAGE_BYTES (2*TILE_HALVES*2)  // A+B per stage = 18432 B
#define GEMM_SMEM   (STAGES*STAGE_BYTES) // 73728 B

// kH2 pipeline: 3-stage ring x (25 rows x 256 cols fp32), i-chunks of 125 rows
#define H2_ROWS   25
#define H2_TILE   (H2_ROWS*256)                  // floats per stage
#define H2_CHUNK  125
#define H2_NSTAGE 5                               // 125 rows per i-chunk
#define H2_SMEM   ((3*H2_TILE + 16*128) * 4)      // 84992 B -> 2 blocks/SM

// ---------------- scratch (device globals; no runtime alloc) ----------------
__device__ float g_S[NN*NN];                 // fixed-adj path only
__device__ __half g_Sh[NN*KPAD];             // fp16 S (pad cols zero)
__device__ __half g_XtT[NCP*KPAD];           // fp16 X^T rows n=b*17+c, cols m
__device__ __half g_Y1T[NCP*KPAD];           // fp16 Y1^T
__device__ float g_rrow[NN];
__device__ float g_Y1[NN*NCP];
__device__ float g_Y2[NN*NCP];
__device__ __half g_Wh[NN*KCQ*O4];           // adaptive weights (fp16, 13 MB)
__device__ float g_bias[NN*OO];
__device__ float g_wws[NN*O8];
__device__ float g_wwt[NN*O2];
__device__ float g_xw[BB*NN];
__device__ float g_se[BB*NE];
__device__ float g_mpT[NE*BB];
__device__ float g_xm[NN*BB];
__device__ float g_rsum[NN];

__device__ __forceinline__ float decode_scalar(const int* p) {
    int iv = *p;
    return (iv > -1000000 && iv < 1000000) ? (float)iv : __int_as_float(iv);
}

__device__ __forceinline__ unsigned cvta_s(const void* p) {
    return (unsigned)__cvta_generic_to_shared(p);
}

// ---------------- fused: S0 = relu(ne@ne^T) diag=stay, softmax -> fp16 S ----------------
// 4 rows/block (R12 proven form: 21.9us; 2-row retile cost +7us — reverted)
__global__ __launch_bounds__(256) void kS0Softmax(const float* __restrict__ ne,
                                                  const float* __restrict__ adj,
                                                  const int* __restrict__ stay,
                                                  const int* __restrict__ fixedp) {
    __shared__ float4 red4[256];
    int i0 = blockIdx.x * 4;
    int t = threadIdx.x;
    bool isfixed = (decode_scalar(fixedp) != 0.0f);
    float sc = decode_scalar(stay);

    float nei[4][16];
#pragma unroll
    for (int r = 0; r < 4; r++)
#pragma unroll
        for (int q = 0; q < 4; q++) {
            float4 v = __ldg((const float4*)&ne[(size_t)(i0 + r) * DD + q * 4]);
            nei[r][q * 4 + 0] = v.x; nei[r][q * 4 + 1] = v.y;
            nei[r][q * 4 + 2] = v.z; nei[r][q * 4 + 3] = v.w;
        }

    float vals[4][8];
    float4 mx = make_float4(-1e30f, -1e30f, -1e30f, -1e30f);
#pragma unroll
    for (int jj = 0; jj < 8; jj++) {
        int j = t + jj * 256;
        if (j < NN) {
            float nej[16];
#pragma unroll
            for (int q = 0; q < 4; q++) {
                float4 v = __ldg((const float4*)&ne[(size_t)j * DD + q * 4]);
                nej[q * 4 + 0] = v.x; nej[q * 4 + 1] = v.y;
                nej[q * 4 + 2] = v.z; nej[q * 4 + 3] = v.w;
            }
#pragma unroll
            for (int r = 0; r < 4; r++) {
                float acc = 0.f;
#pragma unroll
                for (int d = 0; d < 16; d++) acc += nei[r][d] * nej[d];
                vals[r][jj] = (j == i0 + r) ? sc : fmaxf(acc, 0.f);
            }
            mx.x = fmaxf(mx.x, vals[0][jj]); mx.y = fmaxf(mx.y, vals[1][jj]);
            mx.z = fmaxf(mx.z, vals[2][jj]); mx.w = fmaxf(mx.w, vals[3][jj]);
        } else {
#pragma unroll
            for (int r = 0; r < 4; r++) vals[r][jj] = -1e30f;
        }
    }
    red4[t] = mx; __syncthreads();
    for (int s = 128; s > 0; s >>= 1) {
        if (t < s) {
            float4 o = red4[t + s];
            red4[t].x = fmaxf(red4[t].x, o.x); red4[t].y = fmaxf(red4[t].y, o.y);
            red4[t].z = fmaxf(red4[t].z, o.z); red4[t].w = fmaxf(red4[t].w, o.w);
        }
        __syncthreads();
    }
    mx = red4[0]; __syncthreads();
    float mxa[4] = {mx.x, mx.y, mx.z, mx.w};

    float suma[4] = {0.f, 0.f, 0.f, 0.f};
#pragma unroll
    for (int jj = 0; jj < 8; jj++) {
        int j = t + jj * 256;
        if (j < NN) {
#pragma unroll
            for (int r = 0; r < 4; r++) {
                float e;
                if (!isfixed) e = expf(vals[r][jj] - mxa[r]);
                else          e = __ldg(&adj[(size_t)(i0 + r) * NN + j]) * expf(vals[r][jj]);
                vals[r][jj] = e;
                suma[r] += e;
            }
        }
    }
    red4[t] = make_float4(suma[0], suma[1], suma[2], suma[3]); __syncthreads();
    for (int s = 128; s > 0; s >>= 1) {
        if (t < s) {
            float4 o = red4[t + s];
            red4[t].x += o.x; red4[t].y += o.y; red4[t].z += o.z; red4[t].w += o.w;
        }
        __syncthreads();
    }
    float4 sum = red4[0];
    float inv[4] = {1.f / sum.x, 1.f / sum.y, 1.f / sum.z, 1.f / sum.w};

    if (!isfixed) {
#pragma unroll
        for (int jj = 0; jj < 8; jj++) {
            int j = t + jj * 256;
            if (j < NN)
#pragma unroll
                for (int r = 0; r < 4; r++)
                    g_Sh[(size_t)(i0 + r) * KPAD + j] = __float2half(vals[r][jj] * inv[r]);
        }
    } else {
#pragma unroll
        for (int jj = 0; jj < 8; jj++) {
            int j = t + jj * 256;
            if (j < NN)
#pragma unroll
                for (int r = 0; r < 4; r++)
                    g_S[(size_t)(i0 + r) * NN + j] = vals[r][jj];
        }
        if (t < 4) g_rrow[i0 + t] = inv[t];
    }
}

// fixed-adj path only: column j scaled by 1/rowsum[j], emit fp16
__global__ void kColDivH(const int* __restrict__ fixedp) {
    if (decode_scalar(fixedp) == 0.0f) return;
    int idx = blockIdx.x * blockDim.x + threadIdx.x;
    int stride = gridDim.x * blockDim.x;
    for (; idx < NN * NN; idx += stride) {
        int i = idx / NN, j = idx - i * NN;
        g_Sh[(size_t)i * KPAD + j] = __float2half(g_S[idx] * g_rrow[j]);
    }
}

// ---------------- prep: bias/wws/wwt + gnn rowsum + temporal + packT + hodge se/mpT ----------------
__global__ __launch_bounds__(256) void kPrep(const float* __restrict__ ne,
                                             const float* __restrict__ bp,
                                             const float* __restrict__ wwsp,
                                             const float* __restrict__ wwtp,
                                             const float* __restrict__ gw,
                                             const float* __restrict__ xwin,
                                             const float* __restrict__ Tp,
                                             const float* __restrict__ x,
                                             const float* __restrict__ xew,
                                             const int* __restrict__ bidx,
                                             const float* __restrict__ lw,
                                             const float* __restrict__ lb,
                                             const int* __restrict__ jumpp) {
    __shared__ float nn[16];
    __shared__ float red[256];
    int n = blockIdx.x, t = threadIdx.x;
    if (t < 16) nn[t] = ne[n * DD + t];
    __syncthreads();
    {
        float acc = 0.f;
#pragma unroll
        for (int d = 0; d < 16; d++) acc += nn[d] * bp[d * OO + t];
        g_bias[n * OO + t] = acc;
    }
    if (t < O8) {
        float a = 0.f;
#pragma unroll
        for (int d = 0; d < 16; d++) a += nn[d] * wwsp[d * O8 + t];
        g_wws[n * O8 + t] = a;
    }
    if (t < O2) {
        float a = 0.f;
#pragma unroll
        for (int d = 0; d < 16; d++) a += nn[d] * wwtp[d * O2 + t];
        g_wwt[n * O2 + t] = a;
    }
    {
        float s = 0.f;
        for (int j = t; j < NN; j += 256) s += gw[(size_t)n * NN + j];
        red[t] = s; __syncthreads();
        for (int st = 128; st > 0; st >>= 1) { if (t < st) red[t] += red[t + st]; __syncthreads(); }
        if (t == 0) g_rsum[n] = red[0];
    }
    if (t < BB) {
        float s = 0.f;
#pragma unroll
        for (int w = 0; w < WW; w++) s += xwin[(size_t)t * WW * NN + (size_t)w * NN + n] * Tp[w];
        g_xw[t * NN + n] = s;
    }
    for (int l = t; l < BC; l += 256) {
        int b = l / CC, c = l - b * CC;
        g_XtT[(size_t)l * KPAD + n] = __float2half(x[(size_t)(b * NN + n) * CC + c]);
    }
    // hodge se + mpT init: one element per global thread
    {
        int gid = n * 256 + t;
        if (gid < BB * NE) {
            int b = gid / NE, i = gid - b * NE;
            float w0 = lw[0], b0 = lb[0];
            float jc = decode_scalar(jumpp);
            float s = 0.f, tt = 0.f;
#pragma unroll
            for (int f = 0; f < NBB; f++) {
                int wv = bidx[f];
                float v = xew[(size_t)b * WW * NE + (size_t)wv * NE + i] * w0 + b0;
                s += v;
                tt += (float)(NBB - 1 - f) * v;
            }
            g_se[gid] = s;
            g_mpT[i * BB + b] = jc * tt;
        }
    }
}

// ---------------- fp16 MMA GEMM, cp.async 4-stage pipeline: C(2000,320) = S @ B ----------------
__global__ __launch_bounds__(256) void kGemmMMA(int phase) {
    extern __shared__ __half sm[];
    const __half* __restrict__ Bt = phase ? g_Y1T : g_XtT;
    float* __restrict__ Y = phase ? g_Y2 : g_Y1;
    int m0 = blockIdx.x * 64, n0 = blockIdx.y * 64;
    int t = threadIdx.x;
    int wid = t >> 5, lane = t & 31;
    int wm = (wid & 3) * 16, wn = (wid >> 2) * 32;
    float acc[4][4] = {};

    int row0 = t >> 3, seg = t & 7;
    int row1 = row0 + 32;
    int gmA0 = m0 + row0; if (gmA0 > NN - 1) gmA0 = NN - 1;
    int gmA1 = m0 + row1; if (gmA1 > NN - 1) gmA1 = NN - 1;
    const __half* a0p = &g_Sh[(size_t)gmA0 * KPAD + seg * 8];
    const __half* a1p = &g_Sh[(size_t)gmA1 * KPAD + seg * 8];
    const __half* b0p = &Bt[(size_t)(n0 + row0) * KPAD + seg * 8];
    const __half* b1p = &Bt[(size_t)(n0 + row1) * KPAD + seg * 8];

    unsigned smb = cvta_s(sm);
    unsigned dA0 = smb + (row0 * 72 + seg * 8) * 2;
    unsigned dA1 = smb + (row1 * 72 + seg * 8) * 2;
    unsigned dB0 = dA0 + TILE_HALVES * 2;
    unsigned dB1 = dA1 + TILE_HALVES * 2;

    int r = lane & 7, f = lane >> 3;
    unsigned aOff = smb + ((wm + ((f & 1) << 3) + r) * 72 + ((f >> 1) << 3)) * 2;
    unsigned bOff = smb + TILE_HALVES * 2 + ((wn + ((f >> 1) << 3) + r) * 72 + ((f & 1) << 3)) * 2;

#define ISSUE(KC) do {                                                          \
    if ((KC) < KPAD / 64) {                                                     \
        unsigned sb_ = ((KC) & (STAGES - 1)) * STAGE_BYTES;                     \
        size_t off_ = (size_t)(KC) * 64;                                        \
        asm volatile("cp.async.cg.shared.global [%0], [%1], 16;" :: "r"(dA0 + sb_), "l"(a0p + off_)); \
        asm volatile("cp.async.cg.shared.global [%0], [%1], 16;" :: "r"(dA1 + sb_), "l"(a1p + off_)); \
        asm volatile("cp.async.cg.shared.global [%0], [%1], 16;" :: "r"(dB0 + sb_), "l"(b0p + off_)); \
        asm volatile("cp.async.cg.shared.global [%0], [%1], 16;" :: "r"(dB1 + sb_), "l"(b1p + off_)); \
    }                                                                           \
    asm volatile("cp.async.commit_group;");                                     \
} while (0)

    ISSUE(0); ISSUE(1); ISSUE(2);

    for (int kc = 0; kc < KPAD / 64; kc++) {
        asm volatile("cp.async.wait_group %0;" :: "n"(STAGES - 2));
        __syncthreads();
        ISSUE(kc + 3);
        unsigned sb = (kc & (STAGES - 1)) * STAGE_BYTES;
        unsigned aB = aOff + sb, bB = bOff + sb;
#pragma unroll
        for (int ks = 0; ks < 4; ks++) {
            unsigned a0, a1, a2, a3;
            asm volatile("ldmatrix.sync.aligned.m8n8.x4.shared.b16 {%0,%1,%2,%3}, [%4];"
                         : "=r"(a0), "=r"(a1), "=r"(a2), "=r"(a3)
                         : "r"(aB + ks * 32));
            unsigned b00, b01, b10, b11;
            asm volatile("ldmatrix.sync.aligned.m8n8.x4.shared.b16 {%0,%1,%2,%3}, [%4];"
                         : "=r"(b00), "=r"(b01), "=r"(b10), "=r"(b11)
                         : "r"(bB + ks * 32));
            unsigned b20, b21, b30, b31;
            asm volatile("ldmatrix.sync.aligned.m8n8.x4.shared.b16 {%0,%1,%2,%3}, [%4];"
                         : "=r"(b20), "=r"(b21), "=r"(b30), "=r"(b31)
                         : "r"(bB + ks * 32 + 16 * 144));
#define MMA16816(ACC, B0, B1) \
            asm volatile("mma.sync.aligned.m16n8k16.row.col.f32.f16.f16.f32 " \
                "{%0,%1,%2,%3}, {%4,%5,%6,%7}, {%8,%9}, {%0,%1,%2,%3};" \
                : "+f"(ACC[0]), "+f"(ACC[1]), "+f"(ACC[2]), "+f"(ACC[3]) \
                : "r"(a0), "r"(a1), "r"(a2), "r"(a3), "r"(B0), "r"(B1))
            MMA16816(acc[0], b00, b01);
            MMA16816(acc[1], b10, b11);
            MMA16816(acc[2], b20, b21);
            MMA16816(acc[3], b30, b31);
#undef MMA16816
        }
    }
#undef ISSUE

    int grp = lane >> 2, tid4 = lane & 3;
    int r0 = m0 + wm + grp, r1 = r0 + 8;
#pragma unroll
    for (int nj = 0; nj < 4; nj++) {
        int col = n0 + wn + nj * 8 + tid4 * 2;
        if (r0 < NN) {
            *(float2*)&Y[(size_t)r0 * NCP + col] = make_float2(acc[nj][0], acc[nj][1]);
            if (phase == 0) {
                g_Y1T[(size_t)col * KPAD + r0]       = __float2half(acc[nj][0]);
                g_Y1T[(size_t)(col + 1) * KPAD + r0] = __float2half(acc[nj][1]);
            }
        }
        if (r1 < NN) {
            *(float2*)&Y[(size_t)r1 * NCP + col] = make_float2(acc[nj][2], acc[nj][3]);
            if (phase == 0) {
                g_Y1T[(size_t)col * KPAD + r1]       = __float2half(acc[nj][2]);
                g_Y1T[(size_t)(col + 1) * KPAD + r1] = __float2half(acc[nj][3]);
            }
        }
    }
}

// ---------------- adaptive weights (fp16 out, half2 stores) ----------------
__global__ void kWeights(const float* __restrict__ ne, const float* __restrict__ wp) {
    __shared__ float nes[32][17];
    int j0 = blockIdx.x * 512;
    int n0 = blockIdx.y * 32;
    int t = threadIdx.x;
    for (int l = t; l < 32 * 16; l += 256) {
        int r = l >> 4, d = l & 15;
        nes[r][d] = (n0 + r < NN) ? ne[(n0 + r) * DD + d] : 0.f;
    }
    __syncthreads();
    int j = j0 + t * 2;
    if (j < KCQ * O4) {
        float w0[16], w1[16];
        bool ok1 = (j + 1 < KCQ * O4);
#pragma unroll
        for (int d = 0; d < 16; d++) {
            w0[d] = wp[d * (KCQ * O4) + j];
            w1[d] = ok1 ? wp[d * (KCQ * O4) + j + 1] : 0.f;
        }
        for (int r = 0; r < 32; r++) {
            int n = n0 + r;
            if (n >= NN) break;
            float a0 = 0.f, a1 = 0.f;
#pragma unroll
            for (int d = 0; d < 16; d++) { a0 += nes[r][d] * w0[d]; a1 += nes[r][d] * w1[d]; }
            *(__half2*)&g_Wh[(size_t)n * (KCQ * O4) + j] = __floats2half2_rn(a0, a1);
        }
    }
}

// ---------------- hodge GEMV via cp.async pipeline ----------------
// 3-stage ring, 25x256 fp32 per stage, 125-row chunks -> grid (12,24), 2 blocks/SM
__global__ __launch_bounds__(256) void kH2(const float* __restrict__ hodge) {
    extern __shared__ float h2s[];
    float* tile = h2s;                         // [3][25][256]
    float* ses  = h2s + 3 * H2_TILE;           // [16][128]
    int j0 = blockIdx.x * 256;
    int i0 = blockIdx.y * H2_CHUNK;
    int t = threadIdx.x;
    for (int l = t; l < 16 * H2_CHUNK; l += 256) {
        int b = l / H2_CHUNK, ii = l % H2_CHUNK;
        ses[b * 128 + ii] = g_se[b * NE + i0 + ii];
    }
    unsigned smb = cvta_s(tile);

#define H2_ISSUE(S, RING) do {                                                   \
    if ((S) < H2_NSTAGE) {                                                       \
        unsigned dst0 = smb + (RING) * (H2_TILE * 4);                            \
        const float* src0 = hodge + (size_t)(i0 + (S) * H2_ROWS) * NE + j0;      \
        _Pragma("unroll")                                                        \
        for (int it = 0; it < 7; it++) {                                         \
            int idx = t + it * 256;                                              \
            if (idx < H2_ROWS * 64) {                                            \
                int row = idx >> 6, c4 = idx & 63;                               \
                if (j0 + c4 * 4 + 4 <= NE) {                                     \
                    asm volatile("cp.async.cg.shared.global [%0], [%1], 16;" ::  \
                        "r"(dst0 + (unsigned)(row * 256 + c4 * 4) * 4),          \
                        "l"(src0 + (size_t)row * NE + c4 * 4));                  \
                }                                                                \
            }                                                                    \
        }                                                                        \
    }                                                                            \
    asm volatile("cp.async.commit_group;");                                      \
} while (0)

    H2_ISSUE(0, 0); H2_ISSUE(1, 1);

    float acc[16] = {};
    int ring = 0;
    for (int s = 0; s < H2_NSTAGE; s++) {
        asm volatile("cp.async.wait_group %0;" :: "n"(1));
        __syncthreads();
        int nring = (ring + 2 >= 3) ? ring - 1 : ring + 2;
        H2_ISSUE(s + 2, nring);
        const float* tl = tile + ring * H2_TILE + t;
        int ibase = s * H2_ROWS;
#pragma unroll 5
        for (int i = 0; i < H2_ROWS; i++) {
            float h = tl[i * 256];
#pragma unroll
            for (int b = 0; b < 16; b++)
                acc[b] += ses[b * 128 + ibase + i] * h;
        }
        ring = (ring + 1 == 3) ? 0 : ring + 1;
        __syncthreads();
    }
#undef H2_ISSUE

    int j = j0 + t;
    if (j < NE) {
#pragma unroll
        for (int b = 0; b < 16; b++) atomicAdd(&g_mpT[j * BB + b], acc[b]);
    }
}

// xm[n,b] = (1/nb) sum_e mpT[e,b] * inc[n,e]  — float4 staging, guarded tail (NE % 64 != 0)
__global__ void kH3(const float* __restrict__ inc, int nb) {
    __shared__ float incs[16][68];   // row stride 272B (16B multiple)
    __shared__ float mps[64][20];    // row stride 80B (16B multiple)
    int n0 = blockIdx.x * 16;
    int t = threadIdx.x;
    int nr = t >> 4, b = t & 15;
    int ir = t >> 4, ie4 = (t & 15) * 4;    // incs[ir][ie4..ie4+3]
    int me = t >> 2, mb4 = (t & 3) * 4;     // mps[me][mb4..mb4+3]
    float acc = 0.f;
    for (int e0 = 0; e0 < NE; e0 += 64) {
        if (e0 + 64 <= NE) {
            float4 v = *(const float4*)&inc[(size_t)(n0 + ir) * NE + e0 + ie4];
            *(float4*)&incs[ir][ie4] = v;
            float4 w = *(const float4*)&g_mpT[(size_t)(e0 + me) * BB + mb4];
            *(float4*)&mps[me][mb4] = w;
        } else {
#pragma unroll
            for (int k = 0; k < 4; k++) {
                int e = e0 + ie4 + k;
                incs[ir][ie4 + k] = (e < NE) ? inc[(size_t)(n0 + ir) * NE + e] : 0.f;
            }
            bool okm = (e0 + me < NE);
#pragma unroll
            for (int k = 0; k < 4; k++)
                mps[me][mb4 + k] = okm ? g_mpT[(size_t)(e0 + me) * BB + mb4 + k] : 0.f;
        }
        __syncthreads();
#pragma unroll 8
        for (int ee = 0; ee < 64; ee++) acc += incs[nr][ee] * mps[ee][b];
        __syncthreads();
    }
    g_xm[(n0 + nr) * BB + b] = acc / (float)nb;
}

// ---------------- fused output: diffusion (0:64) + ZFC/temporal/supra (64:256) ----------------
__global__ __launch_bounds__(256) void kOut(const float* __restrict__ x,
                                            const float* __restrict__ zin,
                                            const float* __restrict__ gnnb,
                                            float* __restrict__ out) {
    __shared__ float ws[KCQ * O4];
    __shared__ float xs[BB][KCQ + 1];
    int n = blockIdx.x, t = threadIdx.x;
    {
        const uint4* wp4 = (const uint4*)&g_Wh[(size_t)n * (KCQ * O4)];
        for (int l = t; l < 408; l += 256) {
            uint4 v = wp4[l];
            const __half* h = (const __half*)&v;
#pragma unroll
            for (int k = 0; k < 8; k++) ws[l * 8 + k] = __half2float(h[k]);
        }
    }
    for (int l = t; l < BB * KCQ; l += 256) {
        int b = l / KCQ, kc = l % KCQ;
        int k = kc / CC, c = kc % CC;
        float v;
        if (k == 0)      v = x[(size_t)(b * NN + n) * CC + c];
        else if (k == 1) v = g_Y1[(size_t)n * NCP + b * CC + c];
        else             v = g_Y2[(size_t)n * NCP + b * CC + c];
        xs[b][kc] = v;
    }
    __syncthreads();
    {
        int o = t & 63, bq = t >> 6;
        int b0 = bq * 4;
        float a0 = 0.f, a1 = 0.f, a2 = 0.f, a3 = 0.f;
        for (int kc = 0; kc < KCQ; kc++) {
            float w = ws[kc * O4 + o];
            a0 += xs[b0 + 0][kc] * w;
            a1 += xs[b0 + 1][kc] * w;
            a2 += xs[b0 + 2][kc] * w;
            a3 += xs[b0 + 3][kc] * w;
        }
        float bi = g_bias[n * OO + o];
        out[(size_t)((b0 + 0) * NN + n) * OO + o] = a0 + bi;
        out[(size_t)((b0 + 1) * NN + n) * OO + o] = a1 + bi;
        out[(size_t)((b0 + 2) * NN + n) * OO + o] = a2 + bi;
        out[(size_t)((b0 + 3) * NN + n) * OO + o] = a3 + bi;
    }
    if (t < 192) {
        int j = t, o;
        int q = 0; float zr = 0.f, gb = 0.f, wwtv = 0.f, wwsv = 0.f;
        if (j < 32) {
            int k = n * 32 + j;
            q = k / NN; int m = k - q * NN;
            zr = g_rsum[m]; gb = gnnb[m];
            o = 64 + j;
        } else if (j < 160) {
            wwtv = g_wwt[n * O2 + (j - 32)];
            o = 96 + (j - 32);
        } else {
            wwsv = g_wws[n * O8 + (j - 160)];
            o = 224 + (j - 160);
        }
        float bi = g_bias[n * OO + o];
#pragma unroll
        for (int b = 0; b < BB; b++) {
            float v;
            if (j < 32)       v = fmaxf(zin[b * 32 + q] * zr + gb, 0.f);
            else if (j < 160) v = g_xw[b * NN + n] * wwtv;
            else              v = g_xm[n * BB + b] * wwsv;
            out[(size_t)(b * NN + n) * OO + o] = v + bi;
        }
    }
}

// ---------------- launch ----------------
extern "C" void kernel_launch(void* const* d_in, const int* in_sizes, int n_in,
                              void* d_out, int out_size) {
    const float* x     = (const float*)d_in[0];
    const float* xwin  = (const float*)d_in[1];
    const float* ne    = (const float*)d_in[2];
    const int*   fixed = (const int*)  d_in[3];
    const float* adj   = (const float*)d_in[4];
    const int*   stay  = (const int*)  d_in[5];
    const int*   jump  = (const int*)  d_in[6];
    const float* zin   = (const float*)d_in[7];
    const float* hodge = (const float*)d_in[8];
    const float* xew   = (const float*)d_in[9];
    const float* inc   = (const float*)d_in[10];
    const float* wp    = (const float*)d_in[11];
    const float* wwsp  = (const float*)d_in[12];
    const float* wwtp  = (const float*)d_in[13];
    const float* bp    = (const float*)d_in[14];
    const float* Tp    = (const float*)d_in[15];
    const float* lw    = (const float*)d_in[16];
    const float* lb    = (const float*)d_in[17];
    const float* gw    = (const float*)d_in[18];
    const float* gnnb  = (const float*)d_in[19];
    const int*   bidx  = (const int*)  d_in[20];
    float* out = (float*)d_out;
    int nb = in_sizes[20];   // NB = 3

    cudaFuncSetAttribute(kGemmMMA, cudaFuncAttributeMaxDynamicSharedMemorySize, GEMM_SMEM);
    cudaFuncSetAttribute(kH2, cudaFuncAttributeMaxDynamicSharedMemorySize, H2_SMEM);

    // order: capture slot #4 = kPrep — probe the unprofiled prep kernel.
    // deps: kH2 needs kPrep (g_se/g_mpT); GEMMs need kPrep (g_XtT) + softmax (g_Sh) — all satisfied.
    kWeights<<<dim3(7, 63), 256>>>(ne, wp);
    kS0Softmax<<<500, 256>>>(ne, adj, stay, fixed);
    kColDivH<<<148, 256>>>(fixed);           // dead on softmax path
    kPrep<<<NN, 256>>>(ne, bp, wwsp, wwtp, gw, xwin, Tp, x, xew, bidx, lw, lb, jump);
    kH2<<<dim3(12, 24), 256, H2_SMEM>>>(hodge);
    kGemmMMA<<<dim3(32, 5), 256, GEMM_SMEM>>>(0);
    kGemmMMA<<<dim3(32, 5), 256, GEMM_SMEM>>>(1);
    kH3<<<125, 256>>>(inc, nb);
    kOut<<<NN, 256>>>(x, zin, gnnb, out);
}

// round 16
// speedup vs baseline: 1.0304x; 1.0029x over previous
#include <cuda_runtime.h>
#include <cuda_fp16.h>
#include <math.h>

// Problem dims
#define NN   2000
#define NE   3000
#define BB   16
#define CC   17
#define WW   12
#define DD   16
#define OO   256
#define KK   3
#define NBB  3
#define BC   (BB*CC)    // 272
#define NCP  320        // fp32 Y stride
#define KPAD 2048       // fp16 padded k-stride (zero-init padding is load-bearing)
#define KCQ  (KK*CC)    // 51
#define O4   64
#define O8   32
#define O2   128

#define GSTAGES 3
#define TILE_HALVES (64*72)            // one A or B tile in halves
#define STAGE_BYTES (2*TILE_HALVES*2)  // A+B per stage = 18432 B
#define GEMM_SMEM   (GSTAGES*STAGE_BYTES) // 55296 B -> 2 blocks/SM

// kH2 pipeline: 3-stage ring x (25 rows x 256 cols fp32), i-chunks of 125 rows
#define H2_ROWS   25
#define H2_TILE   (H2_ROWS*256)                  // floats per stage
#define H2_CHUNK  125
#define H2_NSTAGE 5                               // 125 rows per i-chunk
#define H2_SMEM   ((3*H2_TILE + 16*128) * 4)      // 84992 B -> 2 blocks/SM

// ---------------- scratch (device globals; no runtime alloc) ----------------
__device__ float g_S[NN*NN];                 // fixed-adj path only
__device__ __half g_Sh[NN*KPAD];             // fp16 S (pad cols zero)
__device__ __half g_XtT[NCP*KPAD];           // fp16 X^T rows n=b*17+c, cols m
__device__ __half g_Y1T[NCP*KPAD];           // fp16 Y1^T
__device__ float g_rrow[NN];
__device__ float g_Y1[NN*NCP];
__device__ float g_Y2[NN*NCP];
__device__ __half g_Wh[NN*KCQ*O4];           // adaptive weights (fp16, 13 MB)
__device__ float g_bias[NN*OO];
__device__ float g_wws[NN*O8];
__device__ float g_wwt[NN*O2];
__device__ float g_xw[BB*NN];
__device__ float g_se[BB*NE];
__device__ float g_mpT[NE*BB];
__device__ float g_xm[NN*BB];
__device__ float g_rsum[NN];

__device__ __forceinline__ float decode_scalar(const int* p) {
    int iv = *p;
    return (iv > -1000000 && iv < 1000000) ? (float)iv : __int_as_float(iv);
}

__device__ __forceinline__ unsigned cvta_s(const void* p) {
    return (unsigned)__cvta_generic_to_shared(p);
}

// ---------------- fused: S0 = relu(ne@ne^T) diag=stay, softmax -> fp16 S ----------------
__global__ __launch_bounds__(256) void kS0Softmax(const float* __restrict__ ne,
                                                  const float* __restrict__ adj,
                                                  const int* __restrict__ stay,
                                                  const int* __restrict__ fixedp) {
    __shared__ float4 red4[256];
    int i0 = blockIdx.x * 4;
    int t = threadIdx.x;
    bool isfixed = (decode_scalar(fixedp) != 0.0f);
    float sc = decode_scalar(stay);

    float nei[4][16];
#pragma unroll
    for (int r = 0; r < 4; r++)
#pragma unroll
        for (int q = 0; q < 4; q++) {
            float4 v = __ldg((const float4*)&ne[(size_t)(i0 + r) * DD + q * 4]);
            nei[r][q * 4 + 0] = v.x; nei[r][q * 4 + 1] = v.y;
            nei[r][q * 4 + 2] = v.z; nei[r][q * 4 + 3] = v.w;
        }

    float vals[4][8];
    float4 mx = make_float4(-1e30f, -1e30f, -1e30f, -1e30f);
#pragma unroll
    for (int jj = 0; jj < 8; jj++) {
        int j = t + jj * 256;
        if (j < NN) {
            float nej[16];
#pragma unroll
            for (int q = 0; q < 4; q++) {
                float4 v = __ldg((const float4*)&ne[(size_t)j * DD + q * 4]);
                nej[q * 4 + 0] = v.x; nej[q * 4 + 1] = v.y;
                nej[q * 4 + 2] = v.z; nej[q * 4 + 3] = v.w;
            }
#pragma unroll
            for (int r = 0; r < 4; r++) {
                float acc = 0.f;
#pragma unroll
                for (int d = 0; d < 16; d++) acc += nei[r][d] * nej[d];
                vals[r][jj] = (j == i0 + r) ? sc : fmaxf(acc, 0.f);
            }
            mx.x = fmaxf(mx.x, vals[0][jj]); mx.y = fmaxf(mx.y, vals[1][jj]);
            mx.z = fmaxf(mx.z, vals[2][jj]); mx.w = fmaxf(mx.w, vals[3][jj]);
        } else {
#pragma unroll
            for (int r = 0; r < 4; r++) vals[r][jj] = -1e30f;
        }
    }
    red4[t] = mx; __syncthreads();
    for (int s = 128; s > 0; s >>= 1) {
        if (t < s) {
            float4 o = red4[t + s];
            red4[t].x = fmaxf(red4[t].x, o.x); red4[t].y = fmaxf(red4[t].y, o.y);
            red4[t].z = fmaxf(red4[t].z, o.z); red4[t].w = fmaxf(red4[t].w, o.w);
        }
        __syncthreads();
    }
    mx = red4[0]; __syncthreads();
    float mxa[4] = {mx.x, mx.y, mx.z, mx.w};

    float suma[4] = {0.f, 0.f, 0.f, 0.f};
#pragma unroll
    for (int jj = 0; jj < 8; jj++) {
        int j = t + jj * 256;
        if (j < NN) {
#pragma unroll
            for (int r = 0; r < 4; r++) {
                float e;
                if (!isfixed) e = expf(vals[r][jj] - mxa[r]);
                else          e = __ldg(&adj[(size_t)(i0 + r) * NN + j]) * expf(vals[r][jj]);
                vals[r][jj] = e;
                suma[r] += e;
            }
        }
    }
    red4[t] = make_float4(suma[0], suma[1], suma[2], suma[3]); __syncthreads();
    for (int s = 128; s > 0; s >>= 1) {
        if (t < s) {
            float4 o = red4[t + s];
            red4[t].x += o.x; red4[t].y += o.y; red4[t].z += o.z; red4[t].w += o.w;
        }
        __syncthreads();
    }
    float4 sum = red4[0];
    float inv[4] = {1.f / sum.x, 1.f / sum.y, 1.f / sum.z, 1.f / sum.w};

    if (!isfixed) {
#pragma unroll
        for (int jj = 0; jj < 8; jj++) {
            int j = t + jj * 256;
            if (j < NN)
#pragma unroll
                for (int r = 0; r < 4; r++)
                    g_Sh[(size_t)(i0 + r) * KPAD + j] = __float2half(vals[r][jj] * inv[r]);
        }
    } else {
#pragma unroll
        for (int jj = 0; jj < 8; jj++) {
            int j = t + jj * 256;
            if (j < NN)
#pragma unroll
                for (int r = 0; r < 4; r++)
                    g_S[(size_t)(i0 + r) * NN + j] = vals[r][jj];
        }
        if (t < 4) g_rrow[i0 + t] = inv[t];
    }
}

// fixed-adj path only: column j scaled by 1/rowsum[j], emit fp16
__global__ void kColDivH(const int* __restrict__ fixedp) {
    if (decode_scalar(fixedp) == 0.0f) return;
    int idx = blockIdx.x * blockDim.x + threadIdx.x;
    int stride = gridDim.x * blockDim.x;
    for (; idx < NN * NN; idx += stride) {
        int i = idx / NN, j = idx - i * NN;
        g_Sh[(size_t)i * KPAD + j] = __float2half(g_S[idx] * g_rrow[j]);
    }
}

// ---------------- prep: bias/wws/wwt + gnn rowsum + temporal + packT + hodge se/mpT ----------------
__global__ __launch_bounds__(256) void kPrep(const float* __restrict__ ne,
                                             const float* __restrict__ bp,
                                             const float* __restrict__ wwsp,
                                             const float* __restrict__ wwtp,
                                             const float* __restrict__ gw,
                                             const float* __restrict__ xwin,
                                             const float* __restrict__ Tp,
                                             const float* __restrict__ x,
                                             const float* __restrict__ xew,
                                             const int* __restrict__ bidx,
                                             const float* __restrict__ lw,
                                             const float* __restrict__ lb,
                                             const int* __restrict__ jumpp) {
    __shared__ float nn[16];
    __shared__ float red[256];
    int n = blockIdx.x, t = threadIdx.x;
    if (t < 16) nn[t] = ne[n * DD + t];
    __syncthreads();
    {
        float acc = 0.f;
#pragma unroll
        for (int d = 0; d < 16; d++) acc += nn[d] * bp[d * OO + t];
        g_bias[n * OO + t] = acc;
    }
    if (t < O8) {
        float a = 0.f;
#pragma unroll
        for (int d = 0; d < 16; d++) a += nn[d] * wwsp[d * O8 + t];
        g_wws[n * O8 + t] = a;
    }
    if (t < O2) {
        float a = 0.f;
#pragma unroll
        for (int d = 0; d < 16; d++) a += nn[d] * wwtp[d * O2 + t];
        g_wwt[n * O2 + t] = a;
    }
    {
        float s = 0.f;
        for (int j = t; j < NN; j += 256) s += gw[(size_t)n * NN + j];
        red[t] = s; __syncthreads();
        for (int st = 128; st > 0; st >>= 1) { if (t < st) red[t] += red[t + st]; __syncthreads(); }
        if (t == 0) g_rsum[n] = red[0];
    }
    if (t < BB) {
        float s = 0.f;
#pragma unroll
        for (int w = 0; w < WW; w++) s += xwin[(size_t)t * WW * NN + (size_t)w * NN + n] * Tp[w];
        g_xw[t * NN + n] = s;
    }
    for (int l = t; l < BC; l += 256) {
        int b = l / CC, c = l - b * CC;
        g_XtT[(size_t)l * KPAD + n] = __float2half(x[(size_t)(b * NN + n) * CC + c]);
    }
    // hodge se + mpT init: one element per global thread
    {
        int gid = n * 256 + t;
        if (gid < BB * NE) {
            int b = gid / NE, i = gid - b * NE;
            float w0 = lw[0], b0 = lb[0];
            float jc = decode_scalar(jumpp);
            float s = 0.f, tt = 0.f;
#pragma unroll
            for (int f = 0; f < NBB; f++) {
                int wv = bidx[f];
                float v = xew[(size_t)b * WW * NE + (size_t)wv * NE + i] * w0 + b0;
                s += v;
                tt += (float)(NBB - 1 - f) * v;
            }
            g_se[gid] = s;
            g_mpT[i * BB + b] = jc * tt;
        }
    }
}

// ---------------- fp16 MMA GEMM, cp.async 3-stage ring (2 blocks/SM): C = S @ B ----------------
__global__ __launch_bounds__(256, 2) void kGemmMMA(int phase) {
    extern __shared__ __half sm[];
    const __half* __restrict__ Bt = phase ? g_Y1T : g_XtT;
    float* __restrict__ Y = phase ? g_Y2 : g_Y1;
    int m0 = blockIdx.x * 64, n0 = blockIdx.y * 64;
    int t = threadIdx.x;
    int wid = t >> 5, lane = t & 31;
    int wm = (wid & 3) * 16, wn = (wid >> 2) * 32;
    float acc[4][4] = {};

    int row0 = t >> 3, seg = t & 7;
    int row1 = row0 + 32;
    int gmA0 = m0 + row0; if (gmA0 > NN - 1) gmA0 = NN - 1;
    int gmA1 = m0 + row1; if (gmA1 > NN - 1) gmA1 = NN - 1;
    const __half* a0p = &g_Sh[(size_t)gmA0 * KPAD + seg * 8];
    const __half* a1p = &g_Sh[(size_t)gmA1 * KPAD + seg * 8];
    const __half* b0p = &Bt[(size_t)(n0 + row0) * KPAD + seg * 8];
    const __half* b1p = &Bt[(size_t)(n0 + row1) * KPAD + seg * 8];

    unsigned smb = cvta_s(sm);
    unsigned dA0 = smb + (row0 * 72 + seg * 8) * 2;
    unsigned dA1 = smb + (row1 * 72 + seg * 8) * 2;
    unsigned dB0 = dA0 + TILE_HALVES * 2;
    unsigned dB1 = dA1 + TILE_HALVES * 2;

    int r = lane & 7, f = lane >> 3;
    unsigned aOff = smb + ((wm + ((f & 1) << 3) + r) * 72 + ((f >> 1) << 3)) * 2;
    unsigned bOff = smb + TILE_HALVES * 2 + ((wn + ((f >> 1) << 3) + r) * 72 + ((f & 1) << 3)) * 2;

#define ISSUE(KC, RING) do {                                                    \
    if ((KC) < KPAD / 64) {                                                     \
        unsigned sb_ = (RING) * STAGE_BYTES;                                    \
        size_t off_ = (size_t)(KC) * 64;                                        \
        asm volatile("cp.async.cg.shared.global [%0], [%1], 16;" :: "r"(dA0 + sb_), "l"(a0p + off_)); \
        asm volatile("cp.async.cg.shared.global [%0], [%1], 16;" :: "r"(dA1 + sb_), "l"(a1p + off_)); \
        asm volatile("cp.async.cg.shared.global [%0], [%1], 16;" :: "r"(dB0 + sb_), "l"(b0p + off_)); \
        asm volatile("cp.async.cg.shared.global [%0], [%1], 16;" :: "r"(dB1 + sb_), "l"(b1p + off_)); \
    }                                                                           \
    asm volatile("cp.async.commit_group;");                                     \
} while (0)

    ISSUE(0, 0); ISSUE(1, 1);

    int ring = 0;
    for (int kc = 0; kc < KPAD / 64; kc++) {
        asm volatile("cp.async.wait_group %0;" :: "n"(1));
        __syncthreads();
        int wring = ring + 2; if (wring >= GSTAGES) wring -= GSTAGES;
        ISSUE(kc + 2, wring);
        unsigned sb = ring * STAGE_BYTES;
        unsigned aB = aOff + sb, bB = bOff + sb;
#pragma unroll
        for (int ks = 0; ks < 4; ks++) {
            unsigned a0, a1, a2, a3;
            asm volatile("ldmatrix.sync.aligned.m8n8.x4.shared.b16 {%0,%1,%2,%3}, [%4];"
                         : "=r"(a0), "=r"(a1), "=r"(a2), "=r"(a3)
                         : "r"(aB + ks * 32));
            unsigned b00, b01, b10, b11;
            asm volatile("ldmatrix.sync.aligned.m8n8.x4.shared.b16 {%0,%1,%2,%3}, [%4];"
                         : "=r"(b00), "=r"(b01), "=r"(b10), "=r"(b11)
                         : "r"(bB + ks * 32));
            unsigned b20, b21, b30, b31;
            asm volatile("ldmatrix.sync.aligned.m8n8.x4.shared.b16 {%0,%1,%2,%3}, [%4];"
                         : "=r"(b20), "=r"(b21), "=r"(b30), "=r"(b31)
                         : "r"(bB + ks * 32 + 16 * 144));
#define MMA16816(ACC, B0, B1) \
            asm volatile("mma.sync.aligned.m16n8k16.row.col.f32.f16.f16.f32 " \
                "{%0,%1,%2,%3}, {%4,%5,%6,%7}, {%8,%9}, {%0,%1,%2,%3};" \
                : "+f"(ACC[0]), "+f"(ACC[1]), "+f"(ACC[2]), "+f"(ACC[3]) \
                : "r"(a0), "r"(a1), "r"(a2), "r"(a3), "r"(B0), "r"(B1))
            MMA16816(acc[0], b00, b01);
            MMA16816(acc[1], b10, b11);
            MMA16816(acc[2], b20, b21);
            MMA16816(acc[3], b30, b31);
#undef MMA16816
        }
        ring = ring + 1; if (ring == GSTAGES) ring = 0;
        __syncthreads();
    }
#undef ISSUE

    int grp = lane >> 2, tid4 = lane & 3;
    int r0 = m0 + wm + grp, r1 = r0 + 8;
#pragma unroll
    for (int nj = 0; nj < 4; nj++) {
        int col = n0 + wn + nj * 8 + tid4 * 2;
        if (r0 < NN) {
            *(float2*)&Y[(size_t)r0 * NCP + col] = make_float2(acc[nj][0], acc[nj][1]);
            if (phase == 0) {
                g_Y1T[(size_t)col * KPAD + r0]       = __float2half(acc[nj][0]);
                g_Y1T[(size_t)(col + 1) * KPAD + r0] = __float2half(acc[nj][1]);
            }
        }
        if (r1 < NN) {
            *(float2*)&Y[(size_t)r1 * NCP + col] = make_float2(acc[nj][2], acc[nj][3]);
            if (phase == 0) {
                g_Y1T[(size_t)col * KPAD + r1]       = __float2half(acc[nj][2]);
                g_Y1T[(size_t)(col + 1) * KPAD + r1] = __float2half(acc[nj][3]);
            }
        }
    }
}

// ---------------- adaptive weights (fp16 out, half2 stores) ----------------
__global__ void kWeights(const float* __restrict__ ne, const float* __restrict__ wp) {
    __shared__ float nes[32][17];
    int j0 = blockIdx.x * 512;
    int n0 = blockIdx.y * 32;
    int t = threadIdx.x;
    for (int l = t; l < 32 * 16; l += 256) {
        int r = l >> 4, d = l & 15;
        nes[r][d] = (n0 + r < NN) ? ne[(n0 + r) * DD + d] : 0.f;
    }
    __syncthreads();
    int j = j0 + t * 2;
    if (j < KCQ * O4) {
        float w0[16], w1[16];
        bool ok1 = (j + 1 < KCQ * O4);
#pragma unroll
        for (int d = 0; d < 16; d++) {
            w0[d] = wp[d * (KCQ * O4) + j];
            w1[d] = ok1 ? wp[d * (KCQ * O4) + j + 1] : 0.f;
        }
        for (int r = 0; r < 32; r++) {
            int n = n0 + r;
            if (n >= NN) break;
            float a0 = 0.f, a1 = 0.f;
#pragma unroll
            for (int d = 0; d < 16; d++) { a0 += nes[r][d] * w0[d]; a1 += nes[r][d] * w1[d]; }
            *(__half2*)&g_Wh[(size_t)n * (KCQ * O4) + j] = __floats2half2_rn(a0, a1);
        }
    }
}

// ---------------- hodge GEMV via cp.async pipeline ----------------
// 3-stage ring, 25x256 fp32 per stage, 125-row chunks -> grid (12,24), 2 blocks/SM
__global__ __launch_bounds__(256) void kH2(const float* __restrict__ hodge) {
    extern __shared__ float h2s[];
    float* tile = h2s;                         // [3][25][256]
    float* ses  = h2s + 3 * H2_TILE;           // [16][128]
    int j0 = blockIdx.x * 256;
    int i0 = blockIdx.y * H2_CHUNK;
    int t = threadIdx.x;
    for (int l = t; l < 16 * H2_CHUNK; l += 256) {
        int b = l / H2_CHUNK, ii = l % H2_CHUNK;
        ses[b * 128 + ii] = g_se[b * NE + i0 + ii];
    }
    unsigned smb = cvta_s(tile);

#define H2_ISSUE(S, RING) do {                                                   \
    if ((S) < H2_NSTAGE) {                                                       \
        unsigned dst0 = smb + (RING) * (H2_TILE * 4);                            \
        const float* src0 = hodge + (size_t)(i0 + (S) * H2_ROWS) * NE + j0;      \
        _Pragma("unroll")                                                        \
        for (int it = 0; it < 7; it++) {                                         \
            int idx = t + it * 256;                                              \
            if (idx < H2_ROWS * 64) {                                            \
                int row = idx >> 6, c4 = idx & 63;                               \
                if (j0 + c4 * 4 + 4 <= NE) {                                     \
                    asm volatile("cp.async.cg.shared.global [%0], [%1], 16;" ::  \
                        "r"(dst0 + (unsigned)(row * 256 + c4 * 4) * 4),          \
                        "l"(src0 + (size_t)row * NE + c4 * 4));                  \
                }                                                                \
            }                                                                    \
        }                                                                        \
    }                                                                            \
    asm volatile("cp.async.commit_group;");                                      \
} while (0)

    H2_ISSUE(0, 0); H2_ISSUE(1, 1);

    float acc[16] = {};
    int ring = 0;
    for (int s = 0; s < H2_NSTAGE; s++) {
        asm volatile("cp.async.wait_group %0;" :: "n"(1));
        __syncthreads();
        int nring = (ring + 2 >= 3) ? ring - 1 : ring + 2;
        H2_ISSUE(s + 2, nring);
        const float* tl = tile + ring * H2_TILE + t;
        int ibase = s * H2_ROWS;
#pragma unroll 5
        for (int i = 0; i < H2_ROWS; i++) {
            float h = tl[i * 256];
#pragma unroll
            for (int b = 0; b < 16; b++)
                acc[b] += ses[b * 128 + ibase + i] * h;
        }
        ring = (ring + 1 == 3) ? 0 : ring + 1;
        __syncthreads();
    }
#undef H2_ISSUE

    int j = j0 + t;
    if (j < NE) {
#pragma unroll
        for (int b = 0; b < 16; b++) atomicAdd(&g_mpT[j * BB + b], acc[b]);
    }
}

// xm[n,b] = (1/nb) sum_e mpT[e,b] * inc[n,e]  — float4 staging, guarded tail (NE % 64 != 0)
__global__ void kH3(const float* __restrict__ inc, int nb) {
    __shared__ float incs[16][68];   // row stride 272B (16B multiple)
    __shared__ float mps[64][20];    // row stride 80B (16B multiple)
    int n0 = blockIdx.x * 16;
    int t = threadIdx.x;
    int nr = t >> 4, b = t & 15;
    int ir = t >> 4, ie4 = (t & 15) * 4;    // incs[ir][ie4..ie4+3]
    int me = t >> 2, mb4 = (t & 3) * 4;     // mps[me][mb4..mb4+3]
    float acc = 0.f;
    for (int e0 = 0; e0 < NE; e0 += 64) {
        if (e0 + 64 <= NE) {
            float4 v = *(const float4*)&inc[(size_t)(n0 + ir) * NE + e0 + ie4];
            *(float4*)&incs[ir][ie4] = v;
            float4 w = *(const float4*)&g_mpT[(size_t)(e0 + me) * BB + mb4];
            *(float4*)&mps[me][mb4] = w;
        } else {
#pragma unroll
            for (int k = 0; k < 4; k++) {
                int e = e0 + ie4 + k;
                incs[ir][ie4 + k] = (e < NE) ? inc[(size_t)(n0 + ir) * NE + e] : 0.f;
            }
            bool okm = (e0 + me < NE);
#pragma unroll
            for (int k = 0; k < 4; k++)
                mps[me][mb4 + k] = okm ? g_mpT[(size_t)(e0 + me) * BB + mb4 + k] : 0.f;
        }
        __syncthreads();
#pragma unroll 8
        for (int ee = 0; ee < 64; ee++) acc += incs[nr][ee] * mps[ee][b];
        __syncthreads();
    }
    g_xm[(n0 + nr) * BB + b] = acc / (float)nb;
}

// ---------------- fused output: diffusion (0:64) + ZFC/temporal/supra (64:256) ----------------
__global__ __launch_bounds__(256) void kOut(const float* __restrict__ x,
                                            const float* __restrict__ zin,
                                            const float* __restrict__ gnnb,
                                            float* __restrict__ out) {
    __shared__ float ws[KCQ * O4];
    __shared__ float xs[BB][KCQ + 1];
    int n = blockIdx.x, t = threadIdx.x;
    {
        const uint4* wp4 = (const uint4*)&g_Wh[(size_t)n * (KCQ * O4)];
        for (int l = t; l < 408; l += 256) {
            uint4 v = wp4[l];
            const __half* h = (const __half*)&v;
#pragma unroll
            for (int k = 0; k < 8; k++) ws[l * 8 + k] = __half2float(h[k]);
        }
    }
    for (int l = t; l < BB * KCQ; l += 256) {
        int b = l / KCQ, kc = l % KCQ;
        int k = kc / CC, c = kc % CC;
        float v;
        if (k == 0)      v = x[(size_t)(b * NN + n) * CC + c];
        else if (k == 1) v = g_Y1[(size_t)n * NCP + b * CC + c];
        else             v = g_Y2[(size_t)n * NCP + b * CC + c];
        xs[b][kc] = v;
    }
    __syncthreads();
    {
        int o = t & 63, bq = t >> 6;
        int b0 = bq * 4;
        float a0 = 0.f, a1 = 0.f, a2 = 0.f, a3 = 0.f;
        for (int kc = 0; kc < KCQ; kc++) {
            float w = ws[kc * O4 + o];
            a0 += xs[b0 + 0][kc] * w;
            a1 += xs[b0 + 1][kc] * w;
            a2 += xs[b0 + 2][kc] * w;
            a3 += xs[b0 + 3][kc] * w;
        }
        float bi = g_bias[n * OO + o];
        out[(size_t)((b0 + 0) * NN + n) * OO + o] = a0 + bi;
        out[(size_t)((b0 + 1) * NN + n) * OO + o] = a1 + bi;
        out[(size_t)((b0 + 2) * NN + n) * OO + o] = a2 + bi;
        out[(size_t)((b0 + 3) * NN + n) * OO + o] = a3 + bi;
    }
    if (t < 192) {
        int j = t, o;
        int q = 0; float zr = 0.f, gb = 0.f, wwtv = 0.f, wwsv = 0.f;
        if (j < 32) {
            int k = n * 32 + j;
            q = k / NN; int m = k - q * NN;
            zr = g_rsum[m]; gb = gnnb[m];
            o = 64 + j;
        } else if (j < 160) {
            wwtv = g_wwt[n * O2 + (j - 32)];
            o = 96 + (j - 32);
        } else {
            wwsv = g_wws[n * O8 + (j - 160)];
            o = 224 + (j - 160);
        }
        float bi = g_bias[n * OO + o];
#pragma unroll
        for (int b = 0; b < BB; b++) {
            float v;
            if (j < 32)       v = fmaxf(zin[b * 32 + q] * zr + gb, 0.f);
            else if (j < 160) v = g_xw[b * NN + n] * wwtv;
            else              v = g_xm[n * BB + b] * wwsv;
            out[(size_t)(b * NN + n) * OO + o] = v + bi;
        }
    }
}

// ---------------- launch ----------------
extern "C" void kernel_launch(void* const* d_in, const int* in_sizes, int n_in,
                              void* d_out, int out_size) {
    const float* x     = (const float*)d_in[0];
    const float* xwin  = (const float*)d_in[1];
    const float* ne    = (const float*)d_in[2];
    const int*   fixed = (const int*)  d_in[3];
    const float* adj   = (const float*)d_in[4];
    const int*   stay  = (const int*)  d_in[5];
    const int*   jump  = (const int*)  d_in[6];
    const float* zin   = (const float*)d_in[7];
    const float* hodge = (const float*)d_in[8];
    const float* xew   = (const float*)d_in[9];
    const float* inc   = (const float*)d_in[10];
    const float* wp    = (const float*)d_in[11];
    const float* wwsp  = (const float*)d_in[12];
    const float* wwtp  = (const float*)d_in[13];
    const float* bp    = (const float*)d_in[14];
    const float* Tp    = (const float*)d_in[15];
    const float* lw    = (const float*)d_in[16];
    const float* lb    = (const float*)d_in[17];
    const float* gw    = (const float*)d_in[18];
    const float* gnnb  = (const float*)d_in[19];
    const int*   bidx  = (const int*)  d_in[20];
    float* out = (float*)d_out;
    int nb = in_sizes[20];   // NB = 3

    cudaFuncSetAttribute(kGemmMMA, cudaFuncAttributeMaxDynamicSharedMemorySize, GEMM_SMEM);
    cudaFuncSetAttribute(kH2, cudaFuncAttributeMaxDynamicSharedMemorySize, H2_SMEM);

    // order: capture slot #4 = kGemmMMA(0) — verify 3-stage/2-blocks-per-SM
    // deps: GEMM needs kPrep (g_XtT) + kS0Softmax (g_Sh); kH2 needs kPrep — all satisfied.
    kPrep<<<NN, 256>>>(ne, bp, wwsp, wwtp, gw, xwin, Tp, x, xew, bidx, lw, lb, jump);
    kS0Softmax<<<500, 256>>>(ne, adj, stay, fixed);
    kColDivH<<<148, 256>>>(fixed);           // dead on softmax path
    kGemmMMA<<<dim3(32, 5), 256, GEMM_SMEM>>>(0);
    kGemmMMA<<<dim3(32, 5), 256, GEMM_SMEM>>>(1);
    kH2<<<dim3(12, 24), 256, H2_SMEM>>>(hodge);
    kWeights<<<dim3(7, 63), 256>>>(ne, wp);
    kH3<<<125, 256>>>(inc, nb);
    kOut<<<NN, 256>>>(x, zin, gnnb, out);
}

// round 17
// speedup vs baseline: 1.0405x; 1.0098x over previous
#include <cuda_runtime.h>
#include <cuda_fp16.h>
#include <math.h>

// Problem dims
#define NN   2000
#define NE   3000
#define BB   16
#define CC   17
#define WW   12
#define DD   16
#define OO   256
#define KK   3
#define NBB  3
#define BC   (BB*CC)    // 272
#define NCP  320        // fp32 Y stride / fp16 [k][n] stride
#define KPAD 2048       // padded k (zero-init padding is load-bearing)
#define KCQ  (KK*CC)    // 51
#define O4   64
#define O8   32
#define O2   128

#define GSTAGES 3
#define TILE_HALVES (64*72)            // one A or B tile in halves
#define STAGE_BYTES (2*TILE_HALVES*2)  // A+B per stage = 18432 B
#define GEMM_SMEM   (GSTAGES*STAGE_BYTES) // 55296 B -> 2 blocks/SM (with max carveout)

// kH2 pipeline: 3-stage ring x (25 rows x 256 cols fp32), i-chunks of 125 rows
#define H2_ROWS   25
#define H2_TILE   (H2_ROWS*256)
#define H2_CHUNK  125
#define H2_NSTAGE 5
#define H2_SMEM   ((3*H2_TILE + 16*128) * 4)      // 84992 B -> 2 blocks/SM

// ---------------- scratch (device globals; no runtime alloc) ----------------
__device__ float g_S[NN*NN];                 // fixed-adj path only
__device__ __half g_Sh[NN*KPAD];             // fp16 S rows m, cols k (pad zero)
__device__ __half g_Xh[KPAD*NCP];            // fp16 X [k=node][n=b*17+c], rows>=NN & cols>=BC stay zero
__device__ __half g_Y1h[KPAD*NCP];           // fp16 Y1 [k][n], rows>=NN stay zero
__device__ float g_rrow[NN];
__device__ float g_Y1[NN*NCP];
__device__ float g_Y2[NN*NCP];
__device__ __half g_Wh[NN*KCQ*O4];           // adaptive weights (fp16, 13 MB)
__device__ float g_bias[NN*OO];
__device__ float g_wws[NN*O8];
__device__ float g_wwt[NN*O2];
__device__ float g_xw[BB*NN];
__device__ float g_se[BB*NE];
__device__ float g_mpT[NE*BB];
__device__ float g_xm[NN*BB];
__device__ float g_rsum[NN];

__device__ __forceinline__ float decode_scalar(const int* p) {
    int iv = *p;
    return (iv > -1000000 && iv < 1000000) ? (float)iv : __int_as_float(iv);
}

__device__ __forceinline__ unsigned cvta_s(const void* p) {
    return (unsigned)__cvta_generic_to_shared(p);
}

// ---------------- fused: S0 = relu(ne@ne^T) diag=stay, softmax -> fp16 S ----------------
__global__ __launch_bounds__(256) void kS0Softmax(const float* __restrict__ ne,
                                                  const float* __restrict__ adj,
                                                  const int* __restrict__ stay,
                                                  const int* __restrict__ fixedp) {
    __shared__ float4 red4[256];
    int i0 = blockIdx.x * 4;
    int t = threadIdx.x;
    bool isfixed = (decode_scalar(fixedp) != 0.0f);
    float sc = decode_scalar(stay);

    float nei[4][16];
#pragma unroll
    for (int r = 0; r < 4; r++)
#pragma unroll
        for (int q = 0; q < 4; q++) {
            float4 v = __ldg((const float4*)&ne[(size_t)(i0 + r) * DD + q * 4]);
            nei[r][q * 4 + 0] = v.x; nei[r][q * 4 + 1] = v.y;
            nei[r][q * 4 + 2] = v.z; nei[r][q * 4 + 3] = v.w;
        }

    float vals[4][8];
    float4 mx = make_float4(-1e30f, -1e30f, -1e30f, -1e30f);
#pragma unroll
    for (int jj = 0; jj < 8; jj++) {
        int j = t + jj * 256;
        if (j < NN) {
            float nej[16];
#pragma unroll
            for (int q = 0; q < 4; q++) {
                float4 v = __ldg((const float4*)&ne[(size_t)j * DD + q * 4]);
                nej[q * 4 + 0] = v.x; nej[q * 4 + 1] = v.y;
                nej[q * 4 + 2] = v.z; nej[q * 4 + 3] = v.w;
            }
#pragma unroll
            for (int r = 0; r < 4; r++) {
                float acc = 0.f;
#pragma unroll
                for (int d = 0; d < 16; d++) acc += nei[r][d] * nej[d];
                vals[r][jj] = (j == i0 + r) ? sc : fmaxf(acc, 0.f);
            }
            mx.x = fmaxf(mx.x, vals[0][jj]); mx.y = fmaxf(mx.y, vals[1][jj]);
            mx.z = fmaxf(mx.z, vals[2][jj]); mx.w = fmaxf(mx.w, vals[3][jj]);
        } else {
#pragma unroll
            for (int r = 0; r < 4; r++) vals[r][jj] = -1e30f;
        }
    }
    red4[t] = mx; __syncthreads();
    for (int s = 128; s > 0; s >>= 1) {
        if (t < s) {
            float4 o = red4[t + s];
            red4[t].x = fmaxf(red4[t].x, o.x); red4[t].y = fmaxf(red4[t].y, o.y);
            red4[t].z = fmaxf(red4[t].z, o.z); red4[t].w = fmaxf(red4[t].w, o.w);
        }
        __syncthreads();
    }
    mx = red4[0]; __syncthreads();
    float mxa[4] = {mx.x, mx.y, mx.z, mx.w};

    float suma[4] = {0.f, 0.f, 0.f, 0.f};
#pragma unroll
    for (int jj = 0; jj < 8; jj++) {
        int j = t + jj * 256;
        if (j < NN) {
#pragma unroll
            for (int r = 0; r < 4; r++) {
                float e;
                if (!isfixed) e = expf(vals[r][jj] - mxa[r]);
                else          e = __ldg(&adj[(size_t)(i0 + r) * NN + j]) * expf(vals[r][jj]);
                vals[r][jj] = e;
                suma[r] += e;
            }
        }
    }
    red4[t] = make_float4(suma[0], suma[1], suma[2], suma[3]); __syncthreads();
    for (int s = 128; s > 0; s >>= 1) {
        if (t < s) {
            float4 o = red4[t + s];
            red4[t].x += o.x; red4[t].y += o.y; red4[t].z += o.z; red4[t].w += o.w;
        }
        __syncthreads();
    }
    float4 sum = red4[0];
    float inv[4] = {1.f / sum.x, 1.f / sum.y, 1.f / sum.z, 1.f / sum.w};

    if (!isfixed) {
#pragma unroll
        for (int jj = 0; jj < 8; jj++) {
            int j = t + jj * 256;
            if (j < NN)
#pragma unroll
                for (int r = 0; r < 4; r++)
                    g_Sh[(size_t)(i0 + r) * KPAD + j] = __float2half(vals[r][jj] * inv[r]);
        }
    } else {
#pragma unroll
        for (int jj = 0; jj < 8; jj++) {
            int j = t + jj * 256;
            if (j < NN)
#pragma unroll
                for (int r = 0; r < 4; r++)
                    g_S[(size_t)(i0 + r) * NN + j] = vals[r][jj];
        }
        if (t < 4) g_rrow[i0 + t] = inv[t];
    }
}

// fixed-adj path only: column j scaled by 1/rowsum[j], emit fp16
__global__ void kColDivH(const int* __restrict__ fixedp) {
    if (decode_scalar(fixedp) == 0.0f) return;
    int idx = blockIdx.x * blockDim.x + threadIdx.x;
    int stride = gridDim.x * blockDim.x;
    for (; idx < NN * NN; idx += stride) {
        int i = idx / NN, j = idx - i * NN;
        g_Sh[(size_t)i * KPAD + j] = __float2half(g_S[idx] * g_rrow[j]);
    }
}

// ---------------- prep: bias/wws/wwt + gnn rowsum + temporal + packX + hodge se/mpT ----------------
__global__ __launch_bounds__(256) void kPrep(const float* __restrict__ ne,
                                             const float* __restrict__ bp,
                                             const float* __restrict__ wwsp,
                                             const float* __restrict__ wwtp,
                                             const float* __restrict__ gw,
                                             const float* __restrict__ xwin,
                                             const float* __restrict__ Tp,
                                             const float* __restrict__ x,
                                             const float* __restrict__ xew,
                                             const int* __restrict__ bidx,
                                             const float* __restrict__ lw,
                                             const float* __restrict__ lb,
                                             const int* __restrict__ jumpp) {
    __shared__ float nn[16];
    __shared__ float red[256];
    int n = blockIdx.x, t = threadIdx.x;
    if (t < 16) nn[t] = ne[n * DD + t];
    __syncthreads();
    {
        float acc = 0.f;
#pragma unroll
        for (int d = 0; d < 16; d++) acc += nn[d] * bp[d * OO + t];
        g_bias[n * OO + t] = acc;
    }
    if (t < O8) {
        float a = 0.f;
#pragma unroll
        for (int d = 0; d < 16; d++) a += nn[d] * wwsp[d * O8 + t];
        g_wws[n * O8 + t] = a;
    }
    if (t < O2) {
        float a = 0.f;
#pragma unroll
        for (int d = 0; d < 16; d++) a += nn[d] * wwtp[d * O2 + t];
        g_wwt[n * O2 + t] = a;
    }
    {
        float s = 0.f;
        for (int j = t; j < NN; j += 256) s += gw[(size_t)n * NN + j];
        red[t] = s; __syncthreads();
        for (int st = 128; st > 0; st >>= 1) { if (t < st) red[t] += red[t + st]; __syncthreads(); }
        if (t == 0) g_rsum[n] = red[0];
    }
    if (t < BB) {
        float s = 0.f;
#pragma unroll
        for (int w = 0; w < WW; w++) s += xwin[(size_t)t * WW * NN + (size_t)w * NN + n] * Tp[w];
        g_xw[t * NN + n] = s;
    }
    // pack X into [k=node][n=b*17+c] fp16 (coalesced row store)
    for (int l = t; l < BC; l += 256) {
        int b = l / CC, c = l - b * CC;
        g_Xh[(size_t)n * NCP + l] = __float2half(x[(size_t)(b * NN + n) * CC + c]);
    }
    // hodge se + mpT init: one element per global thread
    {
        int gid = n * 256 + t;
        if (gid < BB * NE) {
            int b = gid / NE, i = gid - b * NE;
            float w0 = lw[0], b0 = lb[0];
            float jc = decode_scalar(jumpp);
            float s = 0.f, tt = 0.f;
#pragma unroll
            for (int f = 0; f < NBB; f++) {
                int wv = bidx[f];
                float v = xew[(size_t)b * WW * NE + (size_t)wv * NE + i] * w0 + b0;
                s += v;
                tt += (float)(NBB - 1 - f) * v;
            }
            g_se[gid] = s;
            g_mpT[i * BB + b] = jc * tt;
        }
    }
}

// ---------------- fp16 MMA GEMM, cp.async 3-stage ring, [k][n] B layout + ldmatrix.trans ----------------
template<int PHASE>
__global__ __launch_bounds__(256, 2) void kGemmMMA() {
    extern __shared__ __half sm[];
    const __half* __restrict__ Bsrc = PHASE ? g_Y1h : g_Xh;   // [k][NCP] fp16
    float* __restrict__ Y = PHASE ? g_Y2 : g_Y1;
    int m0 = blockIdx.x * 64, n0 = blockIdx.y * 64;
    int t = threadIdx.x;
    int wid = t >> 5, lane = t & 31;
    int wm = (wid & 3) * 16, wn = (wid >> 2) * 32;
    float acc[4][4] = {};

    // loaders: A rows = m (from g_Sh, k contiguous); B rows = k (from Bsrc, n contiguous)
    int row0 = t >> 3, seg = t & 7;
    int row1 = row0 + 32;
    int gmA0 = m0 + row0; if (gmA0 > NN - 1) gmA0 = NN - 1;
    int gmA1 = m0 + row1; if (gmA1 > NN - 1) gmA1 = NN - 1;
    const __half* a0p = &g_Sh[(size_t)gmA0 * KPAD + seg * 8];
    const __half* a1p = &g_Sh[(size_t)gmA1 * KPAD + seg * 8];
    const __half* b0p = &Bsrc[(size_t)row0 * NCP + n0 + seg * 8];   // + kc*64*NCP per chunk
    const __half* b1p = &Bsrc[(size_t)row1 * NCP + n0 + seg * 8];

    unsigned smb = cvta_s(sm);
    unsigned dA0 = smb + (row0 * 72 + seg * 8) * 2;
    unsigned dA1 = smb + (row1 * 72 + seg * 8) * 2;
    unsigned dB0 = dA0 + TILE_HALVES * 2;
    unsigned dB1 = dA1 + TILE_HALVES * 2;

    int r = lane & 7, f = lane >> 3;
    // A (non-trans): rows m, frag order (+0,+0)(+8,+0)(+0,+8)(+8,+8); advance 32B per ks
    unsigned aOff = smb + ((wm + ((f & 1) << 3) + r) * 72 + ((f >> 1) << 3)) * 2;
    // B (trans): smem tile rows k, cols n; matrix f: k-half=(f&1), n-half=(f>>1); advance 16 rows per ks
    unsigned bOffT = smb + TILE_HALVES * 2 + ((((f & 1) << 3) + r) * 72 + wn + ((f >> 1) << 3)) * 2;

#define ISSUE(KC, RING) do {                                                    \
    if ((KC) < KPAD / 64) {                                                     \
        unsigned sb_ = (RING) * STAGE_BYTES;                                    \
        size_t offA_ = (size_t)(KC) * 64;                                       \
        size_t offB_ = (size_t)(KC) * 64 * NCP;                                 \
        asm volatile("cp.async.cg.shared.global [%0], [%1], 16;" :: "r"(dA0 + sb_), "l"(a0p + offA_)); \
        asm volatile("cp.async.cg.shared.global [%0], [%1], 16;" :: "r"(dA1 + sb_), "l"(a1p + offA_)); \
        asm volatile("cp.async.cg.shared.global [%0], [%1], 16;" :: "r"(dB0 + sb_), "l"(b0p + offB_)); \
        asm volatile("cp.async.cg.shared.global [%0], [%1], 16;" :: "r"(dB1 + sb_), "l"(b1p + offB_)); \
    }                                                                           \
    asm volatile("cp.async.commit_group;");                                     \
} while (0)

    ISSUE(0, 0); ISSUE(1, 1);

    int ring = 0;
    for (int kc = 0; kc < KPAD / 64; kc++) {
        asm volatile("cp.async.wait_group %0;" :: "n"(1));
        __syncthreads();
        int wring = ring + 2; if (wring >= GSTAGES) wring -= GSTAGES;
        ISSUE(kc + 2, wring);
        unsigned sb = ring * STAGE_BYTES;
        unsigned aB = aOff + sb;
        unsigned bB = bOffT + sb;
#pragma unroll
        for (int ks = 0; ks < 4; ks++) {
            unsigned a0, a1, a2, a3;
            asm volatile("ldmatrix.sync.aligned.m8n8.x4.shared.b16 {%0,%1,%2,%3}, [%4];"
                         : "=r"(a0), "=r"(a1), "=r"(a2), "=r"(a3)
                         : "r"(aB + ks * 32));
            // B: trans loads from [k][n] tile; ks advances 16 k-rows = 16*144B
            unsigned b00, b01, b10, b11;
            asm volatile("ldmatrix.sync.aligned.m8n8.x4.trans.shared.b16 {%0,%1,%2,%3}, [%4];"
                         : "=r"(b00), "=r"(b01), "=r"(b10), "=r"(b11)
                         : "r"(bB + ks * 2304));
            unsigned b20, b21, b30, b31;
            asm volatile("ldmatrix.sync.aligned.m8n8.x4.trans.shared.b16 {%0,%1,%2,%3}, [%4];"
                         : "=r"(b20), "=r"(b21), "=r"(b30), "=r"(b31)
                         : "r"(bB + ks * 2304 + 32));   // n += 16 cols = 32B
#define MMA16816(ACC, B0, B1) \
            asm volatile("mma.sync.aligned.m16n8k16.row.col.f32.f16.f16.f32 " \
                "{%0,%1,%2,%3}, {%4,%5,%6,%7}, {%8,%9}, {%0,%1,%2,%3};" \
                : "+f"(ACC[0]), "+f"(ACC[1]), "+f"(ACC[2]), "+f"(ACC[3]) \
                : "r"(a0), "r"(a1), "r"(a2), "r"(a3), "r"(B0), "r"(B1))
            MMA16816(acc[0], b00, b01);
            MMA16816(acc[1], b10, b11);
            MMA16816(acc[2], b20, b21);
            MMA16816(acc[3], b30, b31);
#undef MMA16816
        }
        ring = ring + 1; if (ring == GSTAGES) ring = 0;
        __syncthreads();
    }
#undef ISSUE

    int grp = lane >> 2, tid4 = lane & 3;
    int r0 = m0 + wm + grp, r1 = r0 + 8;
#pragma unroll
    for (int nj = 0; nj < 4; nj++) {
        int col = n0 + wn + nj * 8 + tid4 * 2;
        if (r0 < NN) {
            *(float2*)&Y[(size_t)r0 * NCP + col] = make_float2(acc[nj][0], acc[nj][1]);
            if (PHASE == 0)
                *(__half2*)&g_Y1h[(size_t)r0 * NCP + col] = __floats2half2_rn(acc[nj][0], acc[nj][1]);
        }
        if (r1 < NN) {
            *(float2*)&Y[(size_t)r1 * NCP + col] = make_float2(acc[nj][2], acc[nj][3]);
            if (PHASE == 0)
                *(__half2*)&g_Y1h[(size_t)r1 * NCP + col] = __floats2half2_rn(acc[nj][2], acc[nj][3]);
        }
    }
}

// ---------------- adaptive weights (fp16 out, half2 stores) ----------------
__global__ void kWeights(const float* __restrict__ ne, const float* __restrict__ wp) {
    __shared__ float nes[32][17];
    int j0 = blockIdx.x * 512;
    int n0 = blockIdx.y * 32;
    int t = threadIdx.x;
    for (int l = t; l < 32 * 16; l += 256) {
        int r = l >> 4, d = l & 15;
        nes[r][d] = (n0 + r < NN) ? ne[(n0 + r) * DD + d] : 0.f;
    }
    __syncthreads();
    int j = j0 + t * 2;
    if (j < KCQ * O4) {
        float w0[16], w1[16];
        bool ok1 = (j + 1 < KCQ * O4);
#pragma unroll
        for (int d = 0; d < 16; d++) {
            w0[d] = wp[d * (KCQ * O4) + j];
            w1[d] = ok1 ? wp[d * (KCQ * O4) + j + 1] : 0.f;
        }
        for (int r = 0; r < 32; r++) {
            int n = n0 + r;
            if (n >= NN) break;
            float a0 = 0.f, a1 = 0.f;
#pragma unroll
            for (int d = 0; d < 16; d++) { a0 += nes[r][d] * w0[d]; a1 += nes[r][d] * w1[d]; }
            *(__half2*)&g_Wh[(size_t)n * (KCQ * O4) + j] = __floats2half2_rn(a0, a1);
        }
    }
}

// ---------------- hodge GEMV via cp.async pipeline ----------------
__global__ __launch_bounds__(256) void kH2(const float* __restrict__ hodge) {
    extern __shared__ float h2s[];
    float* tile = h2s;                         // [3][25][256]
    float* ses  = h2s + 3 * H2_TILE;           // [16][128]
    int j0 = blockIdx.x * 256;
    int i0 = blockIdx.y * H2_CHUNK;
    int t = threadIdx.x;
    for (int l = t; l < 16 * H2_CHUNK; l += 256) {
        int b = l / H2_CHUNK, ii = l % H2_CHUNK;
        ses[b * 128 + ii] = g_se[b * NE + i0 + ii];
    }
    unsigned smb = cvta_s(tile);

#define H2_ISSUE(S, RING) do {                                                   \
    if ((S) < H2_NSTAGE) {                                                       \
        unsigned dst0 = smb + (RING) * (H2_TILE * 4);                            \
        const float* src0 = hodge + (size_t)(i0 + (S) * H2_ROWS) * NE + j0;      \
        _Pragma("unroll")                                                        \
        for (int it = 0; it < 7; it++) {                                         \
            int idx = t + it * 256;                                              \
            if (idx < H2_ROWS * 64) {                                            \
                int row = idx >> 6, c4 = idx & 63;                               \
                if (j0 + c4 * 4 + 4 <= NE) {                                     \
                    asm volatile("cp.async.cg.shared.global [%0], [%1], 16;" ::  \
                        "r"(dst0 + (unsigned)(row * 256 + c4 * 4) * 4),          \
                        "l"(src0 + (size_t)row * NE + c4 * 4));                  \
                }                                                                \
            }                                                                    \
        }                                                                        \
    }                                                                            \
    asm volatile("cp.async.commit_group;");                                      \
} while (0)

    H2_ISSUE(0, 0); H2_ISSUE(1, 1);

    float acc[16] = {};
    int ring = 0;
    for (int s = 0; s < H2_NSTAGE; s++) {
        asm volatile("cp.async.wait_group %0;" :: "n"(1));
        __syncthreads();
        int nring = (ring + 2 >= 3) ? ring - 1 : ring + 2;
        H2_ISSUE(s + 2, nring);
        const float* tl = tile + ring * H2_TILE + t;
        int ibase = s * H2_ROWS;
#pragma unroll 5
        for (int i = 0; i < H2_ROWS; i++) {
            float h = tl[i * 256];
#pragma unroll
            for (int b = 0; b < 16; b++)
                acc[b] += ses[b * 128 + ibase + i] * h;
        }
        ring = (ring + 1 == 3) ? 0 : ring + 1;
        __syncthreads();
    }
#undef H2_ISSUE

    int j = j0 + t;
    if (j < NE) {
#pragma unroll
        for (int b = 0; b < 16; b++) atomicAdd(&g_mpT[j * BB + b], acc[b]);
    }
}

// xm[n,b] = (1/nb) sum_e mpT[e,b] * inc[n,e]  — float4 staging, guarded tail (NE % 64 != 0)
__global__ void kH3(const float* __restrict__ inc, int nb) {
    __shared__ float incs[16][68];
    __shared__ float mps[64][20];
    int n0 = blockIdx.x * 16;
    int t = threadIdx.x;
    int nr = t >> 4, b = t & 15;
    int ir = t >> 4, ie4 = (t & 15) * 4;
    int me = t >> 2, mb4 = (t & 3) * 4;
    float acc = 0.f;
    for (int e0 = 0; e0 < NE; e0 += 64) {
        if (e0 + 64 <= NE) {
            float4 v = *(const float4*)&inc[(size_t)(n0 + ir) * NE + e0 + ie4];
            *(float4*)&incs[ir][ie4] = v;
            float4 w = *(const float4*)&g_mpT[(size_t)(e0 + me) * BB + mb4];
            *(float4*)&mps[me][mb4] = w;
        } else {
#pragma unroll
            for (int k = 0; k < 4; k++) {
                int e = e0 + ie4 + k;
                incs[ir][ie4 + k] = (e < NE) ? inc[(size_t)(n0 + ir) * NE + e] : 0.f;
            }
            bool okm = (e0 + me < NE);
#pragma unroll
            for (int k = 0; k < 4; k++)
                mps[me][mb4 + k] = okm ? g_mpT[(size_t)(e0 + me) * BB + mb4 + k] : 0.f;
        }
        __syncthreads();
#pragma unroll 8
        for (int ee = 0; ee < 64; ee++) acc += incs[nr][ee] * mps[ee][b];
        __syncthreads();
    }
    g_xm[(n0 + nr) * BB + b] = acc / (float)nb;
}

// ---------------- fused output: diffusion (0:64) + ZFC/temporal/supra (64:256) ----------------
__global__ __launch_bounds__(256) void kOut(const float* __restrict__ x,
                                            const float* __restrict__ zin,
                                            const float* __restrict__ gnnb,
                                            float* __restrict__ out) {
    __shared__ float ws[KCQ * O4];
    __shared__ float xs[BB][KCQ + 1];
    int n = blockIdx.x, t = threadIdx.x;
    {
        const uint4* wp4 = (const uint4*)&g_Wh[(size_t)n * (KCQ * O4)];
        for (int l = t; l < 408; l += 256) {
            uint4 v = wp4[l];
            const __half* h = (const __half*)&v;
#pragma unroll
            for (int k = 0; k < 8; k++) ws[l * 8 + k] = __half2float(h[k]);
        }
    }
    for (int l = t; l < BB * KCQ; l += 256) {
        int b = l / KCQ, kc = l % KCQ;
        int k = kc / CC, c = kc % CC;
        float v;
        if (k == 0)      v = x[(size_t)(b * NN + n) * CC + c];
        else if (k == 1) v = g_Y1[(size_t)n * NCP + b * CC + c];
        else             v = g_Y2[(size_t)n * NCP + b * CC + c];
        xs[b][kc] = v;
    }
    __syncthreads();
    {
        int o = t & 63, bq = t >> 6;
        int b0 = bq * 4;
        float a0 = 0.f, a1 = 0.f, a2 = 0.f, a3 = 0.f;
        for (int kc = 0; kc < KCQ; kc++) {
            float w = ws[kc * O4 + o];
            a0 += xs[b0 + 0][kc] * w;
            a1 += xs[b0 + 1][kc] * w;
            a2 += xs[b0 + 2][kc] * w;
            a3 += xs[b0 + 3][kc] * w;
        }
        float bi = g_bias[n * OO + o];
        out[(size_t)((b0 + 0) * NN + n) * OO + o] = a0 + bi;
        out[(size_t)((b0 + 1) * NN + n) * OO + o] = a1 + bi;
        out[(size_t)((b0 + 2) * NN + n) * OO + o] = a2 + bi;
        out[(size_t)((b0 + 3) * NN + n) * OO + o] = a3 + bi;
    }
    if (t < 192) {
        int j = t, o;
        int q = 0; float zr = 0.f, gb = 0.f, wwtv = 0.f, wwsv = 0.f;
        if (j < 32) {
            int k = n * 32 + j;
            q = k / NN; int m = k - q * NN;
            zr = g_rsum[m]; gb = gnnb[m];
            o = 64 + j;
        } else if (j < 160) {
            wwtv = g_wwt[n * O2 + (j - 32)];
            o = 96 + (j - 32);
        } else {
            wwsv = g_wws[n * O8 + (j - 160)];
            o = 224 + (j - 160);
        }
        float bi = g_bias[n * OO + o];
#pragma unroll
        for (int b = 0; b < BB; b++) {
            float v;
            if (j < 32)       v = fmaxf(zin[b * 32 + q] * zr + gb, 0.f);
            else if (j < 160) v = g_xw[b * NN + n] * wwtv;
            else              v = g_xm[n * BB + b] * wwsv;
            out[(size_t)(b * NN + n) * OO + o] = v + bi;
        }
    }
}

// ---------------- launch ----------------
extern "C" void kernel_launch(void* const* d_in, const int* in_sizes, int n_in,
                              void* d_out, int out_size) {
    const float* x     = (const float*)d_in[0];
    const float* xwin  = (const float*)d_in[1];
    const float* ne    = (const float*)d_in[2];
    const int*   fixed = (const int*)  d_in[3];
    const float* adj   = (const float*)d_in[4];
    const int*   stay  = (const int*)  d_in[5];
    const int*   jump  = (const int*)  d_in[6];
    const float* zin   = (const float*)d_in[7];
    const float* hodge = (const float*)d_in[8];
    const float* xew   = (const float*)d_in[9];
    const float* inc   = (const float*)d_in[10];
    const float* wp    = (const float*)d_in[11];
    const float* wwsp  = (const float*)d_in[12];
    const float* wwtp  = (const float*)d_in[13];
    const float* bp    = (const float*)d_in[14];
    const float* Tp    = (const float*)d_in[15];
    const float* lw    = (const float*)d_in[16];
    const float* lb    = (const float*)d_in[17];
    const float* gw    = (const float*)d_in[18];
    const float* gnnb  = (const float*)d_in[19];
    const int*   bidx  = (const int*)  d_in[20];
    float* out = (float*)d_out;
    int nb = in_sizes[20];   // NB = 3

    cudaFuncSetAttribute(kGemmMMA<0>, cudaFuncAttributeMaxDynamicSharedMemorySize, GEMM_SMEM);
    cudaFuncSetAttribute(kGemmMMA<1>, cudaFuncAttributeMaxDynamicSharedMemorySize, GEMM_SMEM);
    cudaFuncSetAttribute(kGemmMMA<0>, cudaFuncAttributePreferredSharedMemoryCarveout, 100);
    cudaFuncSetAttribute(kGemmMMA<1>, cudaFuncAttributePreferredSharedMemoryCarveout, 100);
    cudaFuncSetAttribute(kH2, cudaFuncAttributeMaxDynamicSharedMemorySize, H2_SMEM);

    // order: capture slot #4 = kGemmMMA<0> — verify trans-B + carveout
    kPrep<<<NN, 256>>>(ne, bp, wwsp, wwtp, gw, xwin, Tp, x, xew, bidx, lw, lb, jump);
    kS0Softmax<<<500, 256>>>(ne, adj, stay, fixed);
    kColDivH<<<148, 256>>>(fixed);           // dead on softmax path
    kGemmMMA<0><<<dim3(32, 5), 256, GEMM_SMEM>>>();
    kGemmMMA<1><<<dim3(32, 5), 256, GEMM_SMEM>>>();
    kH2<<<dim3(12, 24), 256, H2_SMEM>>>(hodge);
    kWeights<<<dim3(7, 63), 256>>>(ne, wp);
    kH3<<<125, 256>>>(inc, nb);
    kOut<<<NN, 256>>>(x, zin, gnnb, out);
}